// round 1
// baseline (speedup 1.0000x reference)
#include <cuda_runtime.h>
#include <cstdint>
#include <math.h>

#define T_TOK   32768      // B*S
#define D_MODEL 512
#define DKc     256
#define DVc     512
#define NH      4
#define HK      64
#define HV      128
#define CH      64         // chunk length
#define NCHUNK  512        // T_TOK / CH (chunks never cross batch: 16384 % 64 == 0)
#define GLR     16

// ---------------- scratch (device globals: allocation-free contract) -------------
__device__ __align__(16) float q_buf [T_TOK*DKc];
__device__ __align__(16) float k_buf [T_TOK*DKc];
__device__ __align__(16) float v_buf [T_TOK*DVc];
__device__ __align__(16) float g_buf [T_TOK*DVc];
__device__ __align__(16) float t1_buf[T_TOK*GLR];
__device__ __align__(16) float gk_buf[T_TOK*DKc];
__device__ __align__(16) float Gc_buf[T_TOK*DKc];
__device__ __align__(16) float U_buf [(size_t)NCHUNK*NH*HK*HV];
__device__ __align__(16) float Hi_buf[(size_t)NCHUNK*NH*HK*HV];
__device__ __align__(16) float o_buf [T_TOK*DVc];

// ---------------- generic fp32 GEMM: C[M,N] = alpha * A[M,K] @ B[K,N] ------------
__global__ void __launch_bounds__(256) gemm_f32(
    const float* __restrict__ A, const float* __restrict__ B,
    float* __restrict__ C, int M, int N, int K, float alpha)
{
    __shared__ float As[16][68];   // [kk][r], padded so float4 rows are aligned
    __shared__ float Bs[16][64];   // [kk][c]
    int tid = threadIdx.x;
    int tx  = tid & 15, ty = tid >> 4;
    int row0 = blockIdx.y << 6, col0 = blockIdx.x << 6;

    float acc[4][4];
#pragma unroll
    for (int i = 0; i < 4; i++)
#pragma unroll
        for (int j = 0; j < 4; j++) acc[i][j] = 0.0f;

    for (int k0 = 0; k0 < K; k0 += 16) {
#pragma unroll
        for (int i = 0; i < 4; i++) {
            int lin = tid + (i << 8);
            int r = lin >> 4, kk = lin & 15;
            As[kk][r] = A[(size_t)(row0 + r) * K + k0 + kk];
        }
#pragma unroll
        for (int i = 0; i < 4; i++) {
            int lin = tid + (i << 8);
            int r = lin >> 6, c = lin & 63;
            int col = col0 + c;
            Bs[r][c] = (col < N) ? B[(size_t)(k0 + r) * N + col] : 0.0f;
        }
        __syncthreads();
#pragma unroll
        for (int kk = 0; kk < 16; kk++) {
            float4 a = *(const float4*)&As[kk][ty << 2];
            float4 b = *(const float4*)&Bs[kk][tx << 2];
            acc[0][0] += a.x*b.x; acc[0][1] += a.x*b.y; acc[0][2] += a.x*b.z; acc[0][3] += a.x*b.w;
            acc[1][0] += a.y*b.x; acc[1][1] += a.y*b.y; acc[1][2] += a.y*b.z; acc[1][3] += a.y*b.w;
            acc[2][0] += a.z*b.x; acc[2][1] += a.z*b.y; acc[2][2] += a.z*b.z; acc[2][3] += a.z*b.w;
            acc[3][0] += a.w*b.x; acc[3][1] += a.w*b.y; acc[3][2] += a.w*b.z; acc[3][3] += a.w*b.w;
        }
        __syncthreads();
    }
#pragma unroll
    for (int i = 0; i < 4; i++) {
        int row = row0 + (ty << 2) + i;
#pragma unroll
        for (int j = 0; j < 4; j++) {
            int col = col0 + (tx << 2) + j;
            if (col < N) C[(size_t)row * N + col] = alpha * acc[i][j];
        }
    }
}

// ---------------- gk = log_sigmoid(t1 @ Wgk2 + b) / 16 --------------------------
__global__ void __launch_bounds__(256) gk_kernel(
    const float* __restrict__ Wgk2, const float* __restrict__ bgk2)
{
    int idx = blockIdx.x * 256 + threadIdx.x;     // over T_TOK*DKc
    int t = idx >> 8, d = idx & 255;
    const float* t1 = &t1_buf[t * GLR];
    float s = bgk2[d];
#pragma unroll
    for (int r = 0; r < GLR; r++) s += t1[r] * Wgk2[r * DKc + d];
    float ls = fminf(s, 0.0f) - log1pf(expf(-fabsf(s)));   // stable log_sigmoid
    gk_buf[idx] = ls * (1.0f / 16.0f);
}

// ---------------- within-chunk inclusive cumsum of gk ----------------------------
__global__ void __launch_bounds__(256) cumsum_kernel()
{
    int gc = blockIdx.x;           // chunk id
    int d  = threadIdx.x;          // key dim
    int base = gc << 6;
    float acc = 0.0f;
#pragma unroll 8
    for (int i = 0; i < CH; i++) {
        acc += gk_buf[(size_t)(base + i) * DKc + d];
        Gc_buf[(size_t)(base + i) * DKc + d] = acc;
    }
}

// ---------------- per-chunk U = sum_t exp(Glast - G_t) k_t (x) v_t ---------------
__global__ void __launch_bounds__(256) chunkU_kernel()
{
    __shared__ __align__(16) float vt[64 * 128];   // v chunk (head slice)
    __shared__ float kt[64 * 64];                  // decayed k (k~)
    int h = blockIdx.x, gc = blockIdx.y;
    int tid = threadIdx.x;
    int t0 = gc << 6;

#pragma unroll
    for (int i = 0; i < 16; i++) {
        int lin = tid + (i << 8);
        int r = lin >> 6, c = lin & 63;
        size_t gidx = (size_t)(t0 + r) * DKc + h * HK + c;
        float glast = Gc_buf[(size_t)(t0 + 63) * DKc + h * HK + c];
        kt[r * 64 + c] = k_buf[gidx] * expf(glast - Gc_buf[gidx]);
    }
    float4* vt4 = (float4*)vt;
#pragma unroll
    for (int i = 0; i < 8; i++) {
        int q = tid + (i << 8);
        int r = q >> 5, c4 = q & 31;
        vt4[q] = *(const float4*)&v_buf[(size_t)(t0 + r) * DVc + h * HV + (c4 << 2)];
    }
    __syncthreads();

    float4* U4 = (float4*)U_buf;
    size_t ub4 = ((size_t)gc * NH + h) << 11;     // *2048 float4s
#pragma unroll
    for (int e = 0; e < 8; e++) {
        int q  = tid + (e << 8);
        int i  = q >> 5, c4 = q & 31;
        float4 acc = make_float4(0.f, 0.f, 0.f, 0.f);
#pragma unroll 8
        for (int t = 0; t < 64; t++) {
            float a   = kt[t * 64 + i];          // warp-broadcast
            float4 v4 = vt4[(t << 5) + c4];      // conflict-free
            acc.x += a * v4.x; acc.y += a * v4.y; acc.z += a * v4.z; acc.w += a * v4.w;
        }
        U4[ub4 + q] = acc;
    }
}

// ---------------- sequential chunk scan: Hi[c]=h ; h = Lam*h + U[c] --------------
__global__ void __launch_bounds__(256) scan_kernel()
{
    int h = blockIdx.x, b = blockIdx.y;
    int tid = threadIdx.x;
    __shared__ float lam[64];
    float4 st[8];
#pragma unroll
    for (int e = 0; e < 8; e++) st[e] = make_float4(0.f, 0.f, 0.f, 0.f);

    float4* Hi4 = (float4*)Hi_buf;
    const float4* U4 = (const float4*)U_buf;
    for (int c = 0; c < 256; c++) {
        int gc = b * 256 + c;
        if (tid < 64)
            lam[tid] = expf(Gc_buf[(size_t)(gc * CH + CH - 1) * DKc + h * HK + tid]);
        __syncthreads();
        size_t b4 = ((size_t)gc * NH + h) << 11;
#pragma unroll
        for (int e = 0; e < 8; e++) {
            int q = tid + (e << 8);
            float l = lam[q >> 5];
            Hi4[b4 + q] = st[e];
            float4 u = U4[b4 + q];
            st[e].x = l * st[e].x + u.x;
            st[e].y = l * st[e].y + u.y;
            st[e].z = l * st[e].z + u.z;
            st[e].w = l * st[e].w + u.w;
        }
        __syncthreads();
    }
}

// ---------------- per-chunk output + LayerNorm + SiLU gate -----------------------
__global__ void __launch_bounds__(256, 2) out_kernel()
{
    extern __shared__ float sm[];
    float* qs = sm;                 // 64*65 : q * exp(G)
    float* ks = sm + 4160;          // 64*65 : k * exp(-G)
    float* As = sm + 8320;          // 64*65 : tril attention
    float* vs = sm + 12480;         // 64*128: v chunk, then h_init (16B-aligned)
    float4* vs4 = (float4*)vs;

    int h = blockIdx.x, gc = blockIdx.y;
    int tid = threadIdx.x;
    int t0 = gc << 6;

#pragma unroll
    for (int i = 0; i < 16; i++) {
        int lin = tid + (i << 8);
        int r = lin >> 6, c = lin & 63;
        size_t gidx = (size_t)(t0 + r) * DKc + h * HK + c;
        float gv = Gc_buf[gidx];
        qs[r * 65 + c] = q_buf[gidx] * expf(gv);
        ks[r * 65 + c] = k_buf[gidx] * expf(-gv);
    }
#pragma unroll
    for (int i = 0; i < 8; i++) {
        int q = tid + (i << 8);
        int r = q >> 5, c4 = q & 31;
        vs4[q] = *(const float4*)&v_buf[(size_t)(t0 + r) * DVc + h * HV + (c4 << 2)];
    }
    __syncthreads();

    // A = tril(qs @ ks^T): 4x4 register tile per thread
    {
        int tt = (tid >> 4) << 2;
        int ss = (tid & 15) << 2;
        float a[4][4];
#pragma unroll
        for (int i = 0; i < 4; i++)
#pragma unroll
            for (int j = 0; j < 4; j++) a[i][j] = 0.0f;
        for (int k = 0; k < 64; k++) {
            float qv[4], kv[4];
#pragma unroll
            for (int i = 0; i < 4; i++) { qv[i] = qs[(tt + i) * 65 + k]; kv[i] = ks[(ss + i) * 65 + k]; }
#pragma unroll
            for (int i = 0; i < 4; i++)
#pragma unroll
                for (int j = 0; j < 4; j++) a[i][j] += qv[i] * kv[j];
        }
#pragma unroll
        for (int i = 0; i < 4; i++)
#pragma unroll
            for (int j = 0; j < 4; j++)
                As[(tt + i) * 65 + ss + j] = (ss + j <= tt + i) ? a[i][j] : 0.0f;
    }
    __syncthreads();

    int t = tid >> 2;
    int jsub = tid & 3;            // thread owns columns j = jsub + 4*jj (broadcast-friendly)
    float o[32];
#pragma unroll
    for (int jj = 0; jj < 32; jj++) o[jj] = 0.0f;

    for (int s = 0; s <= t; s++) {
        float a = As[t * 65 + s];
#pragma unroll
        for (int jj = 0; jj < 32; jj++) o[jj] += a * vs[(s << 7) + jsub + (jj << 2)];
    }
    __syncthreads();

    // reload vs with h_init for this chunk
    {
        size_t hb4 = ((size_t)gc * NH + h) << 11;
        const float4* Hi4 = (const float4*)Hi_buf;
#pragma unroll
        for (int i = 0; i < 8; i++) {
            int q = tid + (i << 8);
            vs4[q] = Hi4[hb4 + q];
        }
    }
    __syncthreads();
#pragma unroll 8
    for (int k = 0; k < 64; k++) {
        float qv = qs[t * 65 + k];
#pragma unroll
        for (int jj = 0; jj < 32; jj++) o[jj] += qv * vs[(k << 7) + jsub + (jj << 2)];
    }

    // LayerNorm over HV=128 (4 threads per row cooperate) + SiLU gate
    float s1 = 0.0f;
#pragma unroll
    for (int jj = 0; jj < 32; jj++) s1 += o[jj];
    s1 += __shfl_xor_sync(0xffffffffu, s1, 1);
    s1 += __shfl_xor_sync(0xffffffffu, s1, 2);
    float mu = s1 * (1.0f / 128.0f);
    float s2 = 0.0f;
#pragma unroll
    for (int jj = 0; jj < 32; jj++) { float d = o[jj] - mu; s2 += d * d; }
    s2 += __shfl_xor_sync(0xffffffffu, s2, 1);
    s2 += __shfl_xor_sync(0xffffffffu, s2, 2);
    float rstd = rsqrtf(s2 * (1.0f / 128.0f) + 1e-5f);

    size_t orow = (size_t)(t0 + t) * DVc + h * HV;
#pragma unroll
    for (int jj = 0; jj < 32; jj++) {
        int j = jsub + (jj << 2);
        float gg = g_buf[orow + j];
        float sg = gg / (1.0f + expf(-gg));      // silu
        o_buf[orow + j] = (o[jj] - mu) * rstd * sg;
    }
}

// ---------------------------------------------------------------------------------
extern "C" void kernel_launch(void* const* d_in, const int* in_sizes, int n_in,
                              void* d_out, int out_size)
{
    const float* x    = (const float*)d_in[0];
    const float* Wq   = (const float*)d_in[1];
    const float* Wk   = (const float*)d_in[2];
    const float* Wv   = (const float*)d_in[3];
    const float* Wg   = (const float*)d_in[4];
    const float* Wgk1 = (const float*)d_in[5];
    const float* Wgk2 = (const float*)d_in[6];
    const float* bgk2 = (const float*)d_in[7];
    const float* Wo   = (const float*)d_in[8];
    float* out = (float*)d_out;
    (void)in_sizes; (void)n_in; (void)out_size;

    void *pq, *pk, *pv, *pg, *pt1, *po;
    cudaGetSymbolAddress(&pq,  q_buf);
    cudaGetSymbolAddress(&pk,  k_buf);
    cudaGetSymbolAddress(&pv,  v_buf);
    cudaGetSymbolAddress(&pg,  g_buf);
    cudaGetSymbolAddress(&pt1, t1_buf);
    cudaGetSymbolAddress(&po,  o_buf);

    const int MT = T_TOK / 64;   // 512 row tiles

    // projections (q scaled by HK^-0.5 = 0.125)
    gemm_f32<<<dim3(DKc/64, MT), 256>>>(x, Wq,   (float*)pq,  T_TOK, DKc,     D_MODEL, 0.125f);
    gemm_f32<<<dim3(DKc/64, MT), 256>>>(x, Wk,   (float*)pk,  T_TOK, DKc,     D_MODEL, 1.0f);
    gemm_f32<<<dim3(DVc/64, MT), 256>>>(x, Wv,   (float*)pv,  T_TOK, DVc,     D_MODEL, 1.0f);
    gemm_f32<<<dim3(DVc/64, MT), 256>>>(x, Wg,   (float*)pg,  T_TOK, DVc,     D_MODEL, 1.0f);
    gemm_f32<<<dim3(1,      MT), 256>>>(x, Wgk1, (float*)pt1, T_TOK, GLR,     D_MODEL, 1.0f);

    gk_kernel<<<T_TOK * DKc / 256, 256>>>(Wgk2, bgk2);
    cumsum_kernel<<<NCHUNK, 256>>>();
    chunkU_kernel<<<dim3(NH, NCHUNK), 256>>>();
    scan_kernel<<<dim3(NH, 2), 256>>>();

    cudaFuncSetAttribute(out_kernel, cudaFuncAttributeMaxDynamicSharedMemorySize, 82688);
    out_kernel<<<dim3(NH, NCHUNK), 256, 82688>>>();

    gemm_f32<<<dim3(D_MODEL/64, MT), 256>>>((const float*)po, Wo, out, T_TOK, D_MODEL, DVc, 1.0f);
}

// round 2
// speedup vs baseline: 1.2815x; 1.2815x over previous
#include <cuda_runtime.h>
#include <cstdint>
#include <math.h>

#define T_TOK   32768      // B*S
#define D_MODEL 512
#define DKc     256
#define DVc     512
#define NH      4
#define HK      64
#define HV      128
#define CH      64
#define NCHUNK  512
#define GLR     16

// ---------------- scratch ---------------------------------------------------------
__device__ __align__(16) float q_buf [T_TOK*DKc];
__device__ __align__(16) float k_buf [T_TOK*DKc];
__device__ __align__(16) float v_buf [T_TOK*DVc];
__device__ __align__(16) float g_buf [T_TOK*DVc];
__device__ __align__(16) float t1_buf[T_TOK*GLR];
__device__ __align__(16) float gk_buf[T_TOK*DKc];
__device__ __align__(16) float Gc_buf[T_TOK*DKc];
__device__ __align__(16) float U_buf [(size_t)NCHUNK*NH*HK*HV];
__device__ __align__(16) float Hi_buf[(size_t)NCHUNK*NH*HK*HV];
__device__ __align__(16) float o_buf [T_TOK*DVc];

// ---------------- 128x128 tile fp32 GEMM, 8x8 microtile ---------------------------
__global__ void __launch_bounds__(256, 2) gemm128(
    const float* __restrict__ A, const float* __restrict__ B,
    float* __restrict__ C, int M, int N, int K, float alpha)
{
    __shared__ float As[16][132];   // [kk][m] transposed
    __shared__ float Bs[16][132];   // [kk][n]
    int tid = threadIdx.x;
    int tx = tid & 15, ty = tid >> 4;
    int row0 = blockIdx.y << 7, col0 = blockIdx.x << 7;

    float acc[8][8];
#pragma unroll
    for (int i = 0; i < 8; i++)
#pragma unroll
        for (int j = 0; j < 8; j++) acc[i][j] = 0.0f;

    int la_r = tid >> 2;            // 0..63 (covers r, r+64)
    int la_k = (tid & 3) << 2;
    int lb_r = tid >> 5;            // 0..7  (covers r, r+8)
    int lb_c = (tid & 31) << 2;

    for (int k0 = 0; k0 < K; k0 += 16) {
#pragma unroll
        for (int i = 0; i < 2; i++) {
            int r = la_r + (i << 6);
            float4 a4 = *(const float4*)&A[(size_t)(row0 + r) * K + k0 + la_k];
            As[la_k + 0][r] = a4.x; As[la_k + 1][r] = a4.y;
            As[la_k + 2][r] = a4.z; As[la_k + 3][r] = a4.w;
        }
#pragma unroll
        for (int i = 0; i < 2; i++) {
            int r = lb_r + (i << 3);
            *(float4*)&Bs[r][lb_c] = *(const float4*)&B[(size_t)(k0 + r) * N + col0 + lb_c];
        }
        __syncthreads();
#pragma unroll
        for (int kk = 0; kk < 16; kk++) {
            float4 a0 = *(const float4*)&As[kk][ty << 2];
            float4 a1 = *(const float4*)&As[kk][(ty << 2) + 64];
            float4 b0 = *(const float4*)&Bs[kk][tx << 2];
            float4 b1 = *(const float4*)&Bs[kk][(tx << 2) + 64];
            float av[8] = {a0.x, a0.y, a0.z, a0.w, a1.x, a1.y, a1.z, a1.w};
            float bv[8] = {b0.x, b0.y, b0.z, b0.w, b1.x, b1.y, b1.z, b1.w};
#pragma unroll
            for (int i = 0; i < 8; i++)
#pragma unroll
                for (int j = 0; j < 8; j++)
                    acc[i][j] += av[i] * bv[j];
        }
        __syncthreads();
    }
#pragma unroll
    for (int i = 0; i < 8; i++) {
        int row = row0 + (ty << 2) + (i & 3) + ((i >> 2) << 6);
        float4 c0 = make_float4(alpha*acc[i][0], alpha*acc[i][1], alpha*acc[i][2], alpha*acc[i][3]);
        float4 c1 = make_float4(alpha*acc[i][4], alpha*acc[i][5], alpha*acc[i][6], alpha*acc[i][7]);
        *(float4*)&C[(size_t)row * N + col0 + (tx << 2)]      = c0;
        *(float4*)&C[(size_t)row * N + col0 + 64 + (tx << 2)] = c1;
    }
}

// ---------------- 64x64 tile GEMM (for N=16 gate projection) ----------------------
__global__ void __launch_bounds__(256) gemm_f32(
    const float* __restrict__ A, const float* __restrict__ B,
    float* __restrict__ C, int M, int N, int K, float alpha)
{
    __shared__ float As[16][68];
    __shared__ float Bs[16][64];
    int tid = threadIdx.x;
    int tx  = tid & 15, ty = tid >> 4;
    int row0 = blockIdx.y << 6, col0 = blockIdx.x << 6;

    float acc[4][4];
#pragma unroll
    for (int i = 0; i < 4; i++)
#pragma unroll
        for (int j = 0; j < 4; j++) acc[i][j] = 0.0f;

    for (int k0 = 0; k0 < K; k0 += 16) {
#pragma unroll
        for (int i = 0; i < 4; i++) {
            int lin = tid + (i << 8);
            int r = lin >> 4, kk = lin & 15;
            As[kk][r] = A[(size_t)(row0 + r) * K + k0 + kk];
        }
#pragma unroll
        for (int i = 0; i < 4; i++) {
            int lin = tid + (i << 8);
            int r = lin >> 6, c = lin & 63;
            int col = col0 + c;
            Bs[r][c] = (col < N) ? B[(size_t)(k0 + r) * N + col] : 0.0f;
        }
        __syncthreads();
#pragma unroll
        for (int kk = 0; kk < 16; kk++) {
            float4 a = *(const float4*)&As[kk][ty << 2];
            float4 b = *(const float4*)&Bs[kk][tx << 2];
            acc[0][0] += a.x*b.x; acc[0][1] += a.x*b.y; acc[0][2] += a.x*b.z; acc[0][3] += a.x*b.w;
            acc[1][0] += a.y*b.x; acc[1][1] += a.y*b.y; acc[1][2] += a.y*b.z; acc[1][3] += a.y*b.w;
            acc[2][0] += a.z*b.x; acc[2][1] += a.z*b.y; acc[2][2] += a.z*b.z; acc[2][3] += a.z*b.w;
            acc[3][0] += a.w*b.x; acc[3][1] += a.w*b.y; acc[3][2] += a.w*b.z; acc[3][3] += a.w*b.w;
        }
        __syncthreads();
    }
#pragma unroll
    for (int i = 0; i < 4; i++) {
        int row = row0 + (ty << 2) + i;
#pragma unroll
        for (int j = 0; j < 4; j++) {
            int col = col0 + (tx << 2) + j;
            if (col < N) C[(size_t)row * N + col] = alpha * acc[i][j];
        }
    }
}

// ---------------- gk = log_sigmoid(t1 @ Wgk2 + b) / 16 ---------------------------
__global__ void __launch_bounds__(256) gk_kernel(
    const float* __restrict__ Wgk2, const float* __restrict__ bgk2)
{
    int idx = blockIdx.x * 256 + threadIdx.x;
    int t = idx >> 8, d = idx & 255;
    const float* t1 = &t1_buf[t * GLR];
    float s = bgk2[d];
#pragma unroll
    for (int r = 0; r < GLR; r++) s += t1[r] * Wgk2[r * DKc + d];
    float ls = fminf(s, 0.0f) - log1pf(expf(-fabsf(s)));
    gk_buf[idx] = ls * (1.0f / 16.0f);
}

// ---------------- within-chunk inclusive cumsum ----------------------------------
__global__ void __launch_bounds__(256) cumsum_kernel()
{
    int gc = blockIdx.x;
    int d  = threadIdx.x;
    int base = gc << 6;
    float acc = 0.0f;
#pragma unroll 8
    for (int i = 0; i < CH; i++) {
        acc += gk_buf[(size_t)(base + i) * DKc + d];
        Gc_buf[(size_t)(base + i) * DKc + d] = acc;
    }
}

// ---------------- per-chunk U = sum_t exp(Glast-G_t) k_t (x) v_t -----------------
// 4x8 register tile GEMM: U[64,128] = kt^T-layout [t][i] @ vt [t][j]
__global__ void __launch_bounds__(256, 2) chunkU_kernel()
{
    extern __shared__ float sm[];
    float* kt = sm;            // [64][68]  (kt[t*68+i] = decayed k)
    float* vt = sm + 4352;     // [64][132]
    int h = blockIdx.x, gc = blockIdx.y;
    int tid = threadIdx.x;
    int tx = tid & 15, ty = tid >> 4;
    int t0 = gc << 6;

#pragma unroll
    for (int i = 0; i < 16; i++) {
        int lin = tid + (i << 8);
        int r = lin >> 6, c = lin & 63;
        size_t gidx = (size_t)(t0 + r) * DKc + h * HK + c;
        float glast = Gc_buf[(size_t)(t0 + 63) * DKc + h * HK + c];
        kt[r * 68 + c] = k_buf[gidx] * expf(glast - Gc_buf[gidx]);
    }
#pragma unroll
    for (int i = 0; i < 8; i++) {
        int q = tid + (i << 8);
        int r = q >> 5, c4 = (q & 31) << 2;
        *(float4*)&vt[r * 132 + c4] =
            *(const float4*)&v_buf[(size_t)(t0 + r) * DVc + h * HV + c4];
    }
    __syncthreads();

    float acc[4][8];
#pragma unroll
    for (int i = 0; i < 4; i++)
#pragma unroll
        for (int j = 0; j < 8; j++) acc[i][j] = 0.0f;

#pragma unroll 4
    for (int t = 0; t < 64; t++) {
        float4 a0 = *(const float4*)&kt[t * 68 + (ty << 2)];
        float4 b0 = *(const float4*)&vt[t * 132 + (tx << 2)];
        float4 b1 = *(const float4*)&vt[t * 132 + 64 + (tx << 2)];
        float av[4] = {a0.x, a0.y, a0.z, a0.w};
        float bv[8] = {b0.x, b0.y, b0.z, b0.w, b1.x, b1.y, b1.z, b1.w};
#pragma unroll
        for (int i = 0; i < 4; i++)
#pragma unroll
            for (int j = 0; j < 8; j++) acc[i][j] += av[i] * bv[j];
    }

    size_t ub = ((size_t)gc * NH + h) << 13;   // *8192
#pragma unroll
    for (int i = 0; i < 4; i++) {
        int row = (ty << 2) + i;
        *(float4*)&U_buf[ub + row * 128 + (tx << 2)] =
            make_float4(acc[i][0], acc[i][1], acc[i][2], acc[i][3]);
        *(float4*)&U_buf[ub + row * 128 + 64 + (tx << 2)] =
            make_float4(acc[i][4], acc[i][5], acc[i][6], acc[i][7]);
    }
}

// ---------------- sequential chunk scan ------------------------------------------
__global__ void __launch_bounds__(256) scan_kernel()
{
    int h = blockIdx.x, b = blockIdx.y;
    int tid = threadIdx.x;
    __shared__ float lam[64];
    float4 st[8];
#pragma unroll
    for (int e = 0; e < 8; e++) st[e] = make_float4(0.f, 0.f, 0.f, 0.f);

    float4* Hi4 = (float4*)Hi_buf;
    const float4* U4 = (const float4*)U_buf;
    for (int c = 0; c < 256; c++) {
        int gc = b * 256 + c;
        if (tid < 64)
            lam[tid] = expf(Gc_buf[(size_t)(gc * CH + CH - 1) * DKc + h * HK + tid]);
        __syncthreads();
        size_t b4 = ((size_t)gc * NH + h) << 11;
#pragma unroll
        for (int e = 0; e < 8; e++) {
            int q = tid + (e << 8);
            float l = lam[q >> 5];
            Hi4[b4 + q] = st[e];
            float4 u = U4[b4 + q];
            st[e].x = l * st[e].x + u.x;
            st[e].y = l * st[e].y + u.y;
            st[e].z = l * st[e].z + u.z;
            st[e].w = l * st[e].w + u.w;
        }
        __syncthreads();
    }
}

// ---------------- per-chunk output + LayerNorm + SiLU gate -----------------------
__global__ void __launch_bounds__(256, 2) out_kernel()
{
    extern __shared__ float sm[];
    float* qs = sm;                 // [64][68] q*exp(G)
    float* ks = sm + 4352;          // [64][65] k*exp(-G)   (dead after A comp)
    float* As = sm + 8512;          // [64][68] tril attention
    float* vs = sm + 12864;         // [64][132] V chunk, then h_init
    float* os = sm + 4352;          // [64][132] output tile (reuses ks+As)

    int h = blockIdx.x, gc = blockIdx.y;
    int tid = threadIdx.x;
    int tx = tid & 15, ty = tid >> 4;
    int t0 = gc << 6;

#pragma unroll
    for (int i = 0; i < 16; i++) {
        int lin = tid + (i << 8);
        int r = lin >> 6, c = lin & 63;
        size_t gidx = (size_t)(t0 + r) * DKc + h * HK + c;
        float gv = Gc_buf[gidx];
        qs[r * 68 + c] = q_buf[gidx] * expf(gv);
        ks[r * 65 + c] = k_buf[gidx] * expf(-gv);
    }
#pragma unroll
    for (int i = 0; i < 8; i++) {
        int q = tid + (i << 8);
        int r = q >> 5, c4 = (q & 31) << 2;
        *(float4*)&vs[r * 132 + c4] =
            *(const float4*)&v_buf[(size_t)(t0 + r) * DVc + h * HV + c4];
    }
    __syncthreads();

    // A = tril(qs @ ks^T), 4x4 register tile
    {
        int tt = (tid >> 4) << 2;
        int ss = (tid & 15) << 2;
        float a[4][4];
#pragma unroll
        for (int i = 0; i < 4; i++)
#pragma unroll
            for (int j = 0; j < 4; j++) a[i][j] = 0.0f;
#pragma unroll 4
        for (int k = 0; k < 64; k++) {
            float qv[4], kv[4];
#pragma unroll
            for (int i = 0; i < 4; i++) { qv[i] = qs[(tt + i) * 68 + k]; kv[i] = ks[(ss + i) * 65 + k]; }
#pragma unroll
            for (int i = 0; i < 4; i++)
#pragma unroll
                for (int j = 0; j < 4; j++) a[i][j] += qv[i] * kv[j];
        }
#pragma unroll
        for (int i = 0; i < 4; i++)
#pragma unroll
            for (int j = 0; j < 4; j++)
                As[(tt + i) * 68 + ss + j] = (ss + j <= tt + i) ? a[i][j] : 0.0f;
    }
    __syncthreads();

    // acc = A @ V  (4x8 register tile, inner 64)
    float acc[4][8];
#pragma unroll
    for (int i = 0; i < 4; i++)
#pragma unroll
        for (int j = 0; j < 8; j++) acc[i][j] = 0.0f;

#pragma unroll 4
    for (int s = 0; s < 64; s++) {
        float4 b0 = *(const float4*)&vs[s * 132 + (tx << 2)];
        float4 b1 = *(const float4*)&vs[s * 132 + 64 + (tx << 2)];
        float av[4];
#pragma unroll
        for (int i = 0; i < 4; i++) av[i] = As[((ty << 2) + i) * 68 + s];
        float bv[8] = {b0.x, b0.y, b0.z, b0.w, b1.x, b1.y, b1.z, b1.w};
#pragma unroll
        for (int i = 0; i < 4; i++)
#pragma unroll
            for (int j = 0; j < 8; j++) acc[i][j] += av[i] * bv[j];
    }
    __syncthreads();

    // reload vs with h_init
    {
        size_t hb = ((size_t)gc * NH + h) << 13;
#pragma unroll
        for (int i = 0; i < 8; i++) {
            int q = tid + (i << 8);
            int r = q >> 5, c4 = (q & 31) << 2;
            *(float4*)&vs[r * 132 + c4] = *(const float4*)&Hi_buf[hb + r * 128 + c4];
        }
    }
    __syncthreads();

    // acc += q~ @ h_init (inner 64)
#pragma unroll 4
    for (int k = 0; k < 64; k++) {
        float4 b0 = *(const float4*)&vs[k * 132 + (tx << 2)];
        float4 b1 = *(const float4*)&vs[k * 132 + 64 + (tx << 2)];
        float av[4];
#pragma unroll
        for (int i = 0; i < 4; i++) av[i] = qs[((ty << 2) + i) * 68 + k];
        float bv[8] = {b0.x, b0.y, b0.z, b0.w, b1.x, b1.y, b1.z, b1.w};
#pragma unroll
        for (int i = 0; i < 4; i++)
#pragma unroll
            for (int j = 0; j < 8; j++) acc[i][j] += av[i] * bv[j];
    }
    __syncthreads();   // qs/As reads done; os overwrites ks/As

    // stash output tile in smem
#pragma unroll
    for (int i = 0; i < 4; i++) {
        int row = (ty << 2) + i;
        *(float4*)&os[row * 132 + (tx << 2)] =
            make_float4(acc[i][0], acc[i][1], acc[i][2], acc[i][3]);
        *(float4*)&os[row * 132 + 64 + (tx << 2)] =
            make_float4(acc[i][4], acc[i][5], acc[i][6], acc[i][7]);
    }
    __syncthreads();

    // LayerNorm + SiLU gate: 4 threads per row
    int t = tid >> 2;
    int jsub = tid & 3;
    float o[32];
#pragma unroll
    for (int jj = 0; jj < 8; jj++) {
        float4 v4 = *(const float4*)&os[t * 132 + (jsub << 5) + (jj << 2)];
        o[jj*4+0] = v4.x; o[jj*4+1] = v4.y; o[jj*4+2] = v4.z; o[jj*4+3] = v4.w;
    }
    float s1 = 0.0f;
#pragma unroll
    for (int jj = 0; jj < 32; jj++) s1 += o[jj];
    s1 += __shfl_xor_sync(0xffffffffu, s1, 1);
    s1 += __shfl_xor_sync(0xffffffffu, s1, 2);
    float mu = s1 * (1.0f / 128.0f);
    float s2 = 0.0f;
#pragma unroll
    for (int jj = 0; jj < 32; jj++) { float d = o[jj] - mu; s2 += d * d; }
    s2 += __shfl_xor_sync(0xffffffffu, s2, 1);
    s2 += __shfl_xor_sync(0xffffffffu, s2, 2);
    float rstd = rsqrtf(s2 * (1.0f / 128.0f) + 1e-5f);

    size_t orow = (size_t)(t0 + t) * DVc + h * HV + (jsub << 5);
#pragma unroll
    for (int jj = 0; jj < 32; jj++) {
        float gg = g_buf[orow + jj];
        float sg = gg / (1.0f + expf(-gg));
        o_buf[orow + jj] = (o[jj] - mu) * rstd * sg;
    }
}

// ---------------------------------------------------------------------------------
extern "C" void kernel_launch(void* const* d_in, const int* in_sizes, int n_in,
                              void* d_out, int out_size)
{
    const float* x    = (const float*)d_in[0];
    const float* Wq   = (const float*)d_in[1];
    const float* Wk   = (const float*)d_in[2];
    const float* Wv   = (const float*)d_in[3];
    const float* Wg   = (const float*)d_in[4];
    const float* Wgk1 = (const float*)d_in[5];
    const float* Wgk2 = (const float*)d_in[6];
    const float* bgk2 = (const float*)d_in[7];
    const float* Wo   = (const float*)d_in[8];
    float* out = (float*)d_out;
    (void)in_sizes; (void)n_in; (void)out_size;

    void *pq, *pk, *pv, *pg, *pt1, *po;
    cudaGetSymbolAddress(&pq,  q_buf);
    cudaGetSymbolAddress(&pk,  k_buf);
    cudaGetSymbolAddress(&pv,  v_buf);
    cudaGetSymbolAddress(&pg,  g_buf);
    cudaGetSymbolAddress(&pt1, t1_buf);
    cudaGetSymbolAddress(&po,  o_buf);

    static bool attr_done = false;
    if (!attr_done) {
        cudaFuncSetAttribute(out_kernel,    cudaFuncAttributeMaxDynamicSharedMemorySize, 85248);
        cudaFuncSetAttribute(chunkU_kernel, cudaFuncAttributeMaxDynamicSharedMemorySize, 51200);
        attr_done = true;
    }

    const int MT128 = T_TOK / 128;   // 256

    gemm128<<<dim3(DKc/128, MT128), 256>>>(x, Wq, (float*)pq, T_TOK, DKc, D_MODEL, 0.125f);
    gemm128<<<dim3(DKc/128, MT128), 256>>>(x, Wk, (float*)pk, T_TOK, DKc, D_MODEL, 1.0f);
    gemm128<<<dim3(DVc/128, MT128), 256>>>(x, Wv, (float*)pv, T_TOK, DVc, D_MODEL, 1.0f);
    gemm128<<<dim3(DVc/128, MT128), 256>>>(x, Wg, (float*)pg, T_TOK, DVc, D_MODEL, 1.0f);
    gemm_f32<<<dim3(1, T_TOK/64), 256>>>(x, Wgk1, (float*)pt1, T_TOK, GLR, D_MODEL, 1.0f);

    gk_kernel<<<T_TOK * DKc / 256, 256>>>(Wgk2, bgk2);
    cumsum_kernel<<<NCHUNK, 256>>>();
    chunkU_kernel<<<dim3(NH, NCHUNK), 256, 51200>>>();
    scan_kernel<<<dim3(NH, 2), 256>>>();
    out_kernel<<<dim3(NH, NCHUNK), 256, 85248>>>();

    gemm128<<<dim3(D_MODEL/128, MT128), 256>>>((const float*)po, Wo, out, T_TOK, D_MODEL, DVc, 1.0f);
}

// round 5
// speedup vs baseline: 1.6000x; 1.2486x over previous
#include <cuda_runtime.h>
#include <cuda_bf16.h>
#include <cstdint>
#include <math.h>

#define T_TOK   32768      // B*S
#define D_MODEL 512
#define DKc     256
#define DVc     512
#define NH      4
#define HK      64
#define HV      128
#define CH      64
#define NCHUNK  512
#define GLR     16

// ---------------- scratch (device globals) ----------------------------------------
__device__ __align__(16) float q_buf [T_TOK*DKc];
__device__ __align__(16) float k_buf [T_TOK*DKc];
__device__ __align__(16) float v_buf [T_TOK*DVc];
__device__ __align__(16) float g_buf [T_TOK*DVc];
__device__ __align__(16) float t1_buf[T_TOK*GLR];
__device__ __align__(16) float gk_buf[T_TOK*DKc];
__device__ __align__(16) float Gc_buf[T_TOK*DKc];
__device__ __align__(16) float U_buf [(size_t)NCHUNK*NH*HK*HV];
__device__ __align__(16) float Hi_buf[(size_t)NCHUNK*NH*HK*HV];

// bf16 split buffers
__device__ __align__(16) __nv_bfloat16 xhi_buf[T_TOK*D_MODEL];
__device__ __align__(16) __nv_bfloat16 xlo_buf[T_TOK*D_MODEL];
__device__ __align__(16) __nv_bfloat16 ohi_buf[T_TOK*DVc];
__device__ __align__(16) __nv_bfloat16 olo_buf[T_TOK*DVc];
// transposed+split weights: Wt[n][k], K=512
__device__ __align__(16) __nv_bfloat16 wq_hi[DKc*D_MODEL],  wq_lo[DKc*D_MODEL];
__device__ __align__(16) __nv_bfloat16 wk_hi[DKc*D_MODEL],  wk_lo[DKc*D_MODEL];
__device__ __align__(16) __nv_bfloat16 wv_hi[DVc*D_MODEL],  wv_lo[DVc*D_MODEL];
__device__ __align__(16) __nv_bfloat16 wg_hi[DVc*D_MODEL],  wg_lo[DVc*D_MODEL];
__device__ __align__(16) __nv_bfloat16 wo_hi[D_MODEL*DVc],  wo_lo[D_MODEL*DVc];

// ================== helpers =======================================================
__device__ __forceinline__ uint32_t s2u(const void* p) {
    uint32_t a;
    asm("{ .reg .u64 t; cvta.to.shared.u64 t, %1; cvt.u32.u64 %0, t; }" : "=r"(a) : "l"(p));
    return a;
}

#define LDSM4(r0, r1, r2, r3, addr) \
    asm volatile("ldmatrix.sync.aligned.m8n8.x4.shared.b16 {%0,%1,%2,%3}, [%4];" \
        : "=r"(r0), "=r"(r1), "=r"(r2), "=r"(r3) : "r"(addr))

#define MMA16816(c, a, b0, b1) \
    asm volatile("mma.sync.aligned.m16n8k16.row.col.f32.bf16.bf16.f32 " \
        "{%0,%1,%2,%3}, {%4,%5,%6,%7}, {%8,%9}, {%0,%1,%2,%3};" \
        : "+f"((c)[0]), "+f"((c)[1]), "+f"((c)[2]), "+f"((c)[3]) \
        : "r"((a)[0]), "r"((a)[1]), "r"((a)[2]), "r"((a)[3]), "r"(b0), "r"(b1))

#define CP_ASYNC16(dst, src) \
    asm volatile("cp.async.cg.shared.global [%0], [%1], 16;" :: "r"(dst), "l"(src))
#define CP_COMMIT()  asm volatile("cp.async.commit_group;" ::: "memory")
#define CP_WAIT1()   asm volatile("cp.async.wait_group 1;" ::: "memory")
#define CP_WAIT0()   asm volatile("cp.async.wait_group 0;" ::: "memory")

// SMEM tile: [128 rows][72 bf16] = 144 B row stride (16r mod 128 distinct ->
// ldmatrix conflict-free without swizzle). A tile then B tile per buffer.
#define ROWB   144
#define TILEB  18432            // 128*144
#define BUFB   36864            // A + B

// ================== split-bf16 HMMA GEMM ==========================================
// C[M,N] = alpha * (Ahi+Alo)[M,512] @ (Bhi+Blo)^T,  B given K-major [N,512].
// 3 passes (hi*hi, hi*lo, lo*hi) = 24 steps of K=64, cp.async double-buffered.
__global__ void __launch_bounds__(256, 2) hmma_gemm(
    const __nv_bfloat16* __restrict__ Ahi, const __nv_bfloat16* __restrict__ Alo,
    const __nv_bfloat16* __restrict__ Bhi, const __nv_bfloat16* __restrict__ Blo,
    float* __restrict__ C, int N, float alpha)
{
    extern __shared__ char smem[];
    uint32_t sb = s2u(smem);
    int tid = threadIdx.x, lane = tid & 31, wid = tid >> 5;
    int m0 = blockIdx.y << 7, n0 = blockIdx.x << 7;
    int wm = wid & 1, wn = wid >> 1;          // warp tile: rows wm*64, cols wn*32

    float acc[4][4][4];
#pragma unroll
    for (int i = 0; i < 4; i++)
#pragma unroll
        for (int j = 0; j < 4; j++)
#pragma unroll
            for (int r = 0; r < 4; r++) acc[i][j][r] = 0.0f;

    // loader: thread -> (row, 4 chunks of 16B)
    int lrow  = tid >> 1;
    int lcb   = (tid & 1) * 4;                 // chunk base 0 or 4 (of 8)
    uint32_t sa_st = lrow * ROWB + lcb * 16;

    // stage one K=64 step into buffer `buf`
    auto stage = [&](int s, int buf) {
        int seg = s >> 3;
        int kk  = (s & 7) << 6;
        const __nv_bfloat16* Ap = (seg == 2) ? Alo : Ahi;
        const __nv_bfloat16* Bp = (seg == 1) ? Blo : Bhi;
        const __nv_bfloat16* ga = Ap + (size_t)(m0 + lrow) * 512 + kk + lcb * 8;
        const __nv_bfloat16* gb = Bp + (size_t)(n0 + lrow) * 512 + kk + lcb * 8;
        uint32_t da = sb + buf * BUFB + sa_st;
        uint32_t db = da + TILEB;
#pragma unroll
        for (int i = 0; i < 4; i++) {
            CP_ASYNC16(da + i * 16, ga + i * 8);
            CP_ASYNC16(db + i * 16, gb + i * 8);
        }
    };

    // ldmatrix lane addressing
    int r8 = lane & 7, j = lane >> 3;
    // A: matrix j -> row + (j&1)*8, colbyte + (j>>1)*16
    uint32_t a_row = (uint32_t)(wm * 64 + (j & 1) * 8 + r8);
    uint32_t a_cb  = (uint32_t)((j >> 1) * 16);
    // B: matrix j -> row + (j>>1)*8, colbyte + (j&1)*16
    uint32_t b_row = (uint32_t)(wn * 32 + (j >> 1) * 8 + r8);
    uint32_t b_cb  = (uint32_t)((j & 1) * 16);

    stage(0, 0);
    CP_COMMIT();

    for (int s = 0; s < 24; s++) {
        int buf = s & 1;
        if (s < 23) { stage(s + 1, buf ^ 1); CP_COMMIT(); CP_WAIT1(); }
        else        { CP_WAIT0(); }
        __syncthreads();

        uint32_t abase = sb + buf * BUFB;
        uint32_t bbase = abase + TILEB;
#pragma unroll
        for (int kq = 0; kq < 4; kq++) {
            uint32_t kb = kq * 32;
            uint32_t ra[4][4], rb[2][4];
#pragma unroll
            for (int mt = 0; mt < 4; mt++) {
                uint32_t ad = abase + (a_row + mt * 16) * ROWB + kb + a_cb;
                LDSM4(ra[mt][0], ra[mt][1], ra[mt][2], ra[mt][3], ad);
            }
#pragma unroll
            for (int bt = 0; bt < 2; bt++) {
                uint32_t bd = bbase + (b_row + bt * 16) * ROWB + kb + b_cb;
                LDSM4(rb[bt][0], rb[bt][1], rb[bt][2], rb[bt][3], bd);
            }
#pragma unroll
            for (int mt = 0; mt < 4; mt++)
#pragma unroll
                for (int nt = 0; nt < 4; nt++)
                    MMA16816(acc[mt][nt], ra[mt],
                             rb[nt >> 1][(nt & 1) * 2], rb[nt >> 1][(nt & 1) * 2 + 1]);
        }
        __syncthreads();
    }

    // epilogue: direct float2 stores
    int erow = lane >> 2;
    int ecol = (lane & 3) * 2;
#pragma unroll
    for (int mt = 0; mt < 4; mt++) {
        int row = m0 + wm * 64 + mt * 16 + erow;
#pragma unroll
        for (int nt = 0; nt < 4; nt++) {
            int col = n0 + wn * 32 + nt * 8 + ecol;
            *(float2*)&C[(size_t)row * N + col] =
                make_float2(alpha * acc[mt][nt][0], alpha * acc[mt][nt][1]);
            *(float2*)&C[(size_t)(row + 8) * N + col] =
                make_float2(alpha * acc[mt][nt][2], alpha * acc[mt][nt][3]);
        }
    }
}

// ---------------- prep: split fp32 -> bf16 hi/lo ----------------------------------
__global__ void __launch_bounds__(256) splitx_kernel(
    const float* __restrict__ src, __nv_bfloat16* __restrict__ hi,
    __nv_bfloat16* __restrict__ lo, int n4)
{
    int i = blockIdx.x * 256 + threadIdx.x;
    if (i >= n4) return;
    float4 v = ((const float4*)src)[i];
    float a[4] = {v.x, v.y, v.z, v.w};
    __nv_bfloat16 h[4], l[4];
#pragma unroll
    for (int j = 0; j < 4; j++) {
        h[j] = __float2bfloat16(a[j]);
        l[j] = __float2bfloat16(a[j] - __bfloat162float(h[j]));
    }
    uint2 ph, pl;
    __nv_bfloat162 h01 = {h[0], h[1]}, h23 = {h[2], h[3]};
    __nv_bfloat162 l01 = {l[0], l[1]}, l23 = {l[2], l[3]};
    ph.x = *(uint32_t*)&h01; ph.y = *(uint32_t*)&h23;
    pl.x = *(uint32_t*)&l01; pl.y = *(uint32_t*)&l23;
    *(uint2*)&hi[(size_t)i * 4] = ph;
    *(uint2*)&lo[(size_t)i * 4] = pl;
}

// ---------------- prep: transpose + split W[512,N] -> Wt_hi/lo[N,512] -------------
__global__ void tsplit_kernel(const float* __restrict__ W,
                              __nv_bfloat16* __restrict__ Th,
                              __nv_bfloat16* __restrict__ Tl, int N)
{
    __shared__ float t[32][33];
    int n0 = blockIdx.x * 32, k0 = blockIdx.y * 32;
    int lx = threadIdx.x, ly = threadIdx.y;   // 32 x 8
#pragma unroll
    for (int i = 0; i < 4; i++) {
        int k = ly + i * 8;
        t[k][lx] = W[(size_t)(k0 + k) * N + n0 + lx];
    }
    __syncthreads();
#pragma unroll
    for (int i = 0; i < 4; i++) {
        int n = ly + i * 8;
        float v = t[lx][n];
        __nv_bfloat16 h = __float2bfloat16(v);
        Th[(size_t)(n0 + n) * 512 + k0 + lx] = h;
        Tl[(size_t)(n0 + n) * 512 + k0 + lx] = __float2bfloat16(v - __bfloat162float(h));
    }
}

// ---------------- 64x64 tile fp32 GEMM (N=16 gate projection only) ----------------
__global__ void __launch_bounds__(256) gemm_f32(
    const float* __restrict__ A, const float* __restrict__ B,
    float* __restrict__ C, int M, int N, int K, float alpha)
{
    __shared__ float As[16][68];
    __shared__ float Bs[16][64];
    int tid = threadIdx.x;
    int tx  = tid & 15, ty = tid >> 4;
    int row0 = blockIdx.y << 6, col0 = blockIdx.x << 6;

    float acc[4][4];
#pragma unroll
    for (int i = 0; i < 4; i++)
#pragma unroll
        for (int j = 0; j < 4; j++) acc[i][j] = 0.0f;

    for (int k0 = 0; k0 < K; k0 += 16) {
#pragma unroll
        for (int i = 0; i < 4; i++) {
            int lin = tid + (i << 8);
            int r = lin >> 4, kk = lin & 15;
            As[kk][r] = A[(size_t)(row0 + r) * K + k0 + kk];
        }
#pragma unroll
        for (int i = 0; i < 4; i++) {
            int lin = tid + (i << 8);
            int r = lin >> 6, c = lin & 63;
            int col = col0 + c;
            Bs[r][c] = (col < N) ? B[(size_t)(k0 + r) * N + col] : 0.0f;
        }
        __syncthreads();
#pragma unroll
        for (int kk = 0; kk < 16; kk++) {
            float4 a = *(const float4*)&As[kk][ty << 2];
            float4 b = *(const float4*)&Bs[kk][tx << 2];
            acc[0][0] += a.x*b.x; acc[0][1] += a.x*b.y; acc[0][2] += a.x*b.z; acc[0][3] += a.x*b.w;
            acc[1][0] += a.y*b.x; acc[1][1] += a.y*b.y; acc[1][2] += a.y*b.z; acc[1][3] += a.y*b.w;
            acc[2][0] += a.z*b.x; acc[2][1] += a.z*b.y; acc[2][2] += a.z*b.z; acc[2][3] += a.z*b.w;
            acc[3][0] += a.w*b.x; acc[3][1] += a.w*b.y; acc[3][2] += a.w*b.z; acc[3][3] += a.w*b.w;
        }
        __syncthreads();
    }
#pragma unroll
    for (int i = 0; i < 4; i++) {
        int row = row0 + (ty << 2) + i;
#pragma unroll
        for (int j = 0; j < 4; j++) {
            int col = col0 + (tx << 2) + j;
            if (col < N) C[(size_t)row * N + col] = alpha * acc[i][j];
        }
    }
}

// ---------------- gk = log_sigmoid(t1 @ Wgk2 + b) / 16 ---------------------------
__global__ void __launch_bounds__(256) gk_kernel(
    const float* __restrict__ Wgk2, const float* __restrict__ bgk2)
{
    int idx = blockIdx.x * 256 + threadIdx.x;
    int t = idx >> 8, d = idx & 255;
    const float* t1 = &t1_buf[t * GLR];
    float s = bgk2[d];
#pragma unroll
    for (int r = 0; r < GLR; r++) s += t1[r] * Wgk2[r * DKc + d];
    float ls = fminf(s, 0.0f) - log1pf(expf(-fabsf(s)));
    gk_buf[idx] = ls * (1.0f / 16.0f);
}

// ---------------- within-chunk inclusive cumsum ----------------------------------
__global__ void __launch_bounds__(256) cumsum_kernel()
{
    int gc = blockIdx.x;
    int d  = threadIdx.x;
    int base = gc << 6;
    float acc = 0.0f;
#pragma unroll 8
    for (int i = 0; i < CH; i++) {
        acc += gk_buf[(size_t)(base + i) * DKc + d];
        Gc_buf[(size_t)(base + i) * DKc + d] = acc;
    }
}

// ---------------- per-chunk U = sum_t exp(Glast-G_t) k_t (x) v_t -----------------
__global__ void __launch_bounds__(256, 2) chunkU_kernel()
{
    extern __shared__ float sm[];
    float* kt = sm;            // [64][68]
    float* vt = sm + 4352;     // [64][132]
    int h = blockIdx.x, gc = blockIdx.y;
    int tid = threadIdx.x;
    int tx = tid & 15, ty = tid >> 4;
    int t0 = gc << 6;

#pragma unroll
    for (int i = 0; i < 16; i++) {
        int lin = tid + (i << 8);
        int r = lin >> 6, c = lin & 63;
        size_t gidx = (size_t)(t0 + r) * DKc + h * HK + c;
        float glast = Gc_buf[(size_t)(t0 + 63) * DKc + h * HK + c];
        kt[r * 68 + c] = k_buf[gidx] * expf(glast - Gc_buf[gidx]);
    }
#pragma unroll
    for (int i = 0; i < 8; i++) {
        int q = tid + (i << 8);
        int r = q >> 5, c4 = (q & 31) << 2;
        *(float4*)&vt[r * 132 + c4] =
            *(const float4*)&v_buf[(size_t)(t0 + r) * DVc + h * HV + c4];
    }
    __syncthreads();

    float acc[4][8];
#pragma unroll
    for (int i = 0; i < 4; i++)
#pragma unroll
        for (int j = 0; j < 8; j++) acc[i][j] = 0.0f;

#pragma unroll 4
    for (int t = 0; t < 64; t++) {
        float4 a0 = *(const float4*)&kt[t * 68 + (ty << 2)];
        float4 b0 = *(const float4*)&vt[t * 132 + (tx << 2)];
        float4 b1 = *(const float4*)&vt[t * 132 + 64 + (tx << 2)];
        float av[4] = {a0.x, a0.y, a0.z, a0.w};
        float bv[8] = {b0.x, b0.y, b0.z, b0.w, b1.x, b1.y, b1.z, b1.w};
#pragma unroll
        for (int i = 0; i < 4; i++)
#pragma unroll
            for (int j = 0; j < 8; j++) acc[i][j] += av[i] * bv[j];
    }

    size_t ub = ((size_t)gc * NH + h) << 13;
#pragma unroll
    for (int i = 0; i < 4; i++) {
        int row = (ty << 2) + i;
        *(float4*)&U_buf[ub + row * 128 + (tx << 2)] =
            make_float4(acc[i][0], acc[i][1], acc[i][2], acc[i][3]);
        *(float4*)&U_buf[ub + row * 128 + 64 + (tx << 2)] =
            make_float4(acc[i][4], acc[i][5], acc[i][6], acc[i][7]);
    }
}

// ---------------- sequential chunk scan ------------------------------------------
__global__ void __launch_bounds__(256) scan_kernel()
{
    int h = blockIdx.x, b = blockIdx.y;
    int tid = threadIdx.x;
    __shared__ float lam[64];
    float4 st[8];
#pragma unroll
    for (int e = 0; e < 8; e++) st[e] = make_float4(0.f, 0.f, 0.f, 0.f);

    float4* Hi4 = (float4*)Hi_buf;
    const float4* U4 = (const float4*)U_buf;
    for (int c = 0; c < 256; c++) {
        int gc = b * 256 + c;
        if (tid < 64)
            lam[tid] = expf(Gc_buf[(size_t)(gc * CH + CH - 1) * DKc + h * HK + tid]);
        __syncthreads();
        size_t b4 = ((size_t)gc * NH + h) << 11;
#pragma unroll
        for (int e = 0; e < 8; e++) {
            int q = tid + (e << 8);
            float l = lam[q >> 5];
            Hi4[b4 + q] = st[e];
            float4 u = U4[b4 + q];
            st[e].x = l * st[e].x + u.x;
            st[e].y = l * st[e].y + u.y;
            st[e].z = l * st[e].z + u.z;
            st[e].w = l * st[e].w + u.w;
        }
        __syncthreads();
    }
}

// ---------------- per-chunk output + LN + SiLU, writes bf16 hi/lo ----------------
__global__ void __launch_bounds__(256, 2) out_kernel()
{
    extern __shared__ float sm[];
    float* qs = sm;                 // [64][68]
    float* ks = sm + 4352;          // [64][65]
    float* As = sm + 8512;          // [64][68]
    float* vs = sm + 12864;         // [64][132]
    float* os = sm + 4352;          // [64][132] reuse

    int h = blockIdx.x, gc = blockIdx.y;
    int tid = threadIdx.x;
    int tx = tid & 15, ty = tid >> 4;
    int t0 = gc << 6;

#pragma unroll
    for (int i = 0; i < 16; i++) {
        int lin = tid + (i << 8);
        int r = lin >> 6, c = lin & 63;
        size_t gidx = (size_t)(t0 + r) * DKc + h * HK + c;
        float gv = Gc_buf[gidx];
        qs[r * 68 + c] = q_buf[gidx] * expf(gv);
        ks[r * 65 + c] = k_buf[gidx] * expf(-gv);
    }
#pragma unroll
    for (int i = 0; i < 8; i++) {
        int q = tid + (i << 8);
        int r = q >> 5, c4 = (q & 31) << 2;
        *(float4*)&vs[r * 132 + c4] =
            *(const float4*)&v_buf[(size_t)(t0 + r) * DVc + h * HV + c4];
    }
    __syncthreads();

    {
        int tt = (tid >> 4) << 2;
        int ss = (tid & 15) << 2;
        float a[4][4];
#pragma unroll
        for (int i = 0; i < 4; i++)
#pragma unroll
            for (int j = 0; j < 4; j++) a[i][j] = 0.0f;
#pragma unroll 4
        for (int k = 0; k < 64; k++) {
            float qv[4], kv[4];
#pragma unroll
            for (int i = 0; i < 4; i++) { qv[i] = qs[(tt + i) * 68 + k]; kv[i] = ks[(ss + i) * 65 + k]; }
#pragma unroll
            for (int i = 0; i < 4; i++)
#pragma unroll
                for (int j = 0; j < 4; j++) a[i][j] += qv[i] * kv[j];
        }
#pragma unroll
        for (int i = 0; i < 4; i++)
#pragma unroll
            for (int j = 0; j < 4; j++)
                As[(tt + i) * 68 + ss + j] = (ss + j <= tt + i) ? a[i][j] : 0.0f;
    }
    __syncthreads();

    float acc[4][8];
#pragma unroll
    for (int i = 0; i < 4; i++)
#pragma unroll
        for (int j = 0; j < 8; j++) acc[i][j] = 0.0f;

#pragma unroll 4
    for (int s = 0; s < 64; s++) {
        float4 b0 = *(const float4*)&vs[s * 132 + (tx << 2)];
        float4 b1 = *(const float4*)&vs[s * 132 + 64 + (tx << 2)];
        float av[4];
#pragma unroll
        for (int i = 0; i < 4; i++) av[i] = As[((ty << 2) + i) * 68 + s];
        float bv[8] = {b0.x, b0.y, b0.z, b0.w, b1.x, b1.y, b1.z, b1.w};
#pragma unroll
        for (int i = 0; i < 4; i++)
#pragma unroll
            for (int j = 0; j < 8; j++) acc[i][j] += av[i] * bv[j];
    }
    __syncthreads();

    {
        size_t hb = ((size_t)gc * NH + h) << 13;
#pragma unroll
        for (int i = 0; i < 8; i++) {
            int q = tid + (i << 8);
            int r = q >> 5, c4 = (q & 31) << 2;
            *(float4*)&vs[r * 132 + c4] = *(const float4*)&Hi_buf[hb + r * 128 + c4];
        }
    }
    __syncthreads();

#pragma unroll 4
    for (int k = 0; k < 64; k++) {
        float4 b0 = *(const float4*)&vs[k * 132 + (tx << 2)];
        float4 b1 = *(const float4*)&vs[k * 132 + 64 + (tx << 2)];
        float av[4];
#pragma unroll
        for (int i = 0; i < 4; i++) av[i] = qs[((ty << 2) + i) * 68 + k];
        float bv[8] = {b0.x, b0.y, b0.z, b0.w, b1.x, b1.y, b1.z, b1.w};
#pragma unroll
        for (int i = 0; i < 4; i++)
#pragma unroll
            for (int j = 0; j < 8; j++) acc[i][j] += av[i] * bv[j];
    }
    __syncthreads();

#pragma unroll
    for (int i = 0; i < 4; i++) {
        int row = (ty << 2) + i;
        *(float4*)&os[row * 132 + (tx << 2)] =
            make_float4(acc[i][0], acc[i][1], acc[i][2], acc[i][3]);
        *(float4*)&os[row * 132 + 64 + (tx << 2)] =
            make_float4(acc[i][4], acc[i][5], acc[i][6], acc[i][7]);
    }
    __syncthreads();

    int t = tid >> 2;
    int jsub = tid & 3;
    float o[32];
#pragma unroll
    for (int jj = 0; jj < 8; jj++) {
        float4 v4 = *(const float4*)&os[t * 132 + (jsub << 5) + (jj << 2)];
        o[jj*4+0] = v4.x; o[jj*4+1] = v4.y; o[jj*4+2] = v4.z; o[jj*4+3] = v4.w;
    }
    float s1 = 0.0f;
#pragma unroll
    for (int jj = 0; jj < 32; jj++) s1 += o[jj];
    s1 += __shfl_xor_sync(0xffffffffu, s1, 1);
    s1 += __shfl_xor_sync(0xffffffffu, s1, 2);
    float mu = s1 * (1.0f / 128.0f);
    float s2 = 0.0f;
#pragma unroll
    for (int jj = 0; jj < 32; jj++) { float d = o[jj] - mu; s2 += d * d; }
    s2 += __shfl_xor_sync(0xffffffffu, s2, 1);
    s2 += __shfl_xor_sync(0xffffffffu, s2, 2);
    float rstd = rsqrtf(s2 * (1.0f / 128.0f) + 1e-5f);

    size_t orow = (size_t)(t0 + t) * DVc + h * HV + (jsub << 5);
#pragma unroll
    for (int jj = 0; jj < 32; jj++) {
        float gg = g_buf[orow + jj];
        float sg = gg / (1.0f + expf(-gg));
        float val = (o[jj] - mu) * rstd * sg;
        __nv_bfloat16 hb = __float2bfloat16(val);
        ohi_buf[orow + jj] = hb;
        olo_buf[orow + jj] = __float2bfloat16(val - __bfloat162float(hb));
    }
}

// ---------------------------------------------------------------------------------
extern "C" void kernel_launch(void* const* d_in, const int* in_sizes, int n_in,
                              void* d_out, int out_size)
{
    const float* x    = (const float*)d_in[0];
    const float* Wq   = (const float*)d_in[1];
    const float* Wk   = (const float*)d_in[2];
    const float* Wv   = (const float*)d_in[3];
    const float* Wg   = (const float*)d_in[4];
    const float* Wgk1 = (const float*)d_in[5];
    const float* Wgk2 = (const float*)d_in[6];
    const float* bgk2 = (const float*)d_in[7];
    const float* Wo   = (const float*)d_in[8];
    float* out = (float*)d_out;
    (void)in_sizes; (void)n_in; (void)out_size;

    void *pq, *pk, *pv, *pg, *pt1;
    void *pxh, *pxl, *poh, *pol;
    void *pwqh, *pwql, *pwkh, *pwkl, *pwvh, *pwvl, *pwgh, *pwgl, *pwoh, *pwol;
    cudaGetSymbolAddress(&pq,  q_buf);
    cudaGetSymbolAddress(&pk,  k_buf);
    cudaGetSymbolAddress(&pv,  v_buf);
    cudaGetSymbolAddress(&pg,  g_buf);
    cudaGetSymbolAddress(&pt1, t1_buf);
    cudaGetSymbolAddress(&pxh, xhi_buf);
    cudaGetSymbolAddress(&pxl, xlo_buf);
    cudaGetSymbolAddress(&poh, ohi_buf);
    cudaGetSymbolAddress(&pol, olo_buf);
    cudaGetSymbolAddress(&pwqh, wq_hi); cudaGetSymbolAddress(&pwql, wq_lo);
    cudaGetSymbolAddress(&pwkh, wk_hi); cudaGetSymbolAddress(&pwkl, wk_lo);
    cudaGetSymbolAddress(&pwvh, wv_hi); cudaGetSymbolAddress(&pwvl, wv_lo);
    cudaGetSymbolAddress(&pwgh, wg_hi); cudaGetSymbolAddress(&pwgl, wg_lo);
    cudaGetSymbolAddress(&pwoh, wo_hi); cudaGetSymbolAddress(&pwol, wo_lo);

    cudaFuncSetAttribute(hmma_gemm,     cudaFuncAttributeMaxDynamicSharedMemorySize, 2 * BUFB);
    cudaFuncSetAttribute(out_kernel,    cudaFuncAttributeMaxDynamicSharedMemorySize, 85248);
    cudaFuncSetAttribute(chunkU_kernel, cudaFuncAttributeMaxDynamicSharedMemorySize, 51200);

    typedef const __nv_bfloat16* cbf;

    // prep: split x, transpose+split weights
    splitx_kernel<<<T_TOK * D_MODEL / 4 / 256, 256>>>(x, (__nv_bfloat16*)pxh, (__nv_bfloat16*)pxl,
                                                      T_TOK * D_MODEL / 4);
    tsplit_kernel<<<dim3(DKc/32, 16), dim3(32, 8)>>>(Wq, (__nv_bfloat16*)pwqh, (__nv_bfloat16*)pwql, DKc);
    tsplit_kernel<<<dim3(DKc/32, 16), dim3(32, 8)>>>(Wk, (__nv_bfloat16*)pwkh, (__nv_bfloat16*)pwkl, DKc);
    tsplit_kernel<<<dim3(DVc/32, 16), dim3(32, 8)>>>(Wv, (__nv_bfloat16*)pwvh, (__nv_bfloat16*)pwvl, DVc);
    tsplit_kernel<<<dim3(DVc/32, 16), dim3(32, 8)>>>(Wg, (__nv_bfloat16*)pwgh, (__nv_bfloat16*)pwgl, DVc);
    tsplit_kernel<<<dim3(D_MODEL/32, 16), dim3(32, 8)>>>(Wo, (__nv_bfloat16*)pwoh, (__nv_bfloat16*)pwol, D_MODEL);

    const int MT = T_TOK / 128;   // 256

    hmma_gemm<<<dim3(DKc/128, MT), 256, 2*BUFB>>>((cbf)pxh, (cbf)pxl, (cbf)pwqh, (cbf)pwql,
                                                  (float*)pq, DKc, 0.125f);
    hmma_gemm<<<dim3(DKc/128, MT), 256, 2*BUFB>>>((cbf)pxh, (cbf)pxl, (cbf)pwkh, (cbf)pwkl,
                                                  (float*)pk, DKc, 1.0f);
    hmma_gemm<<<dim3(DVc/128, MT), 256, 2*BUFB>>>((cbf)pxh, (cbf)pxl, (cbf)pwvh, (cbf)pwvl,
                                                  (float*)pv, DVc, 1.0f);
    hmma_gemm<<<dim3(DVc/128, MT), 256, 2*BUFB>>>((cbf)pxh, (cbf)pxl, (cbf)pwgh, (cbf)pwgl,
                                                  (float*)pg, DVc, 1.0f);
    gemm_f32<<<dim3(1, T_TOK/64), 256>>>(x, Wgk1, (float*)pt1, T_TOK, GLR, D_MODEL, 1.0f);

    gk_kernel<<<T_TOK * DKc / 256, 256>>>(Wgk2, bgk2);
    cumsum_kernel<<<NCHUNK, 256>>>();
    chunkU_kernel<<<dim3(NH, NCHUNK), 256, 51200>>>();
    scan_kernel<<<dim3(NH, 2), 256>>>();
    out_kernel<<<dim3(NH, NCHUNK), 256, 85248>>>();

    hmma_gemm<<<dim3(D_MODEL/128, MT), 256, 2*BUFB>>>((cbf)poh, (cbf)pol, (cbf)pwoh, (cbf)pwol,
                                                      out, D_MODEL, 1.0f);
}

// round 8
// speedup vs baseline: 2.2677x; 1.4173x over previous
#include <cuda_runtime.h>
#include <cuda_bf16.h>
#include <cstdint>
#include <math.h>

#define T_TOK   32768      // B*S
#define D_MODEL 512
#define DKc     256
#define DVc     512
#define NH      4
#define HK      64
#define HV      128
#define CH      64
#define NCHUNK  512
#define GLR     16
#define NQKVG   1536       // 256 q + 256 k + 512 v + 512 g

// ---------------- scratch (device globals) ----------------------------------------
__device__ __align__(16) float qkvg_buf[(size_t)T_TOK*NQKVG];
__device__ __align__(16) float t1_buf [T_TOK*GLR];
__device__ __align__(16) float eg_buf [T_TOK*DKc];
__device__ __align__(16) float einv_buf[T_TOK*DKc];
__device__ __align__(16) float U_buf [(size_t)NCHUNK*NH*HK*HV];
__device__ __align__(16) float Hi_buf[(size_t)NCHUNK*NH*HK*HV];

__device__ __align__(16) __nv_bfloat16 xhi_buf[T_TOK*D_MODEL];
__device__ __align__(16) __nv_bfloat16 xlo_buf[T_TOK*D_MODEL];
__device__ __align__(16) __nv_bfloat16 ohi_buf[T_TOK*DVc];
__device__ __align__(16) __nv_bfloat16 olo_buf[T_TOK*DVc];
__device__ __align__(16) __nv_bfloat16 wcat_hi[NQKVG*D_MODEL], wcat_lo[NQKVG*D_MODEL];
__device__ __align__(16) __nv_bfloat16 wo_hi[D_MODEL*DVc],     wo_lo[D_MODEL*DVc];

// ================== FMA-only transcendentals (avoid the slow MUFU pipe) ===========
__device__ __forceinline__ float fexp(float x) {
    float n = rintf(x * 1.4426950408889634f);
    float r = fmaf(n, -0.693359375f, x);
    r = fmaf(n, 2.12194440054690583e-4f, r);
    float p = 1.3888888888e-3f;
    p = fmaf(p, r, 8.3333333333e-3f);
    p = fmaf(p, r, 4.1666666666e-2f);
    p = fmaf(p, r, 1.6666666666e-1f);
    p = fmaf(p, r, 0.5f);
    p = fmaf(p, r, 1.0f);
    p = fmaf(p, r, 1.0f);
    int ni = (int)n;
    return p * __int_as_float((ni + 127) << 23);
}
// log(1+u) for u in (0, 1]
__device__ __forceinline__ float flog1p(float u) {
    bool big = u > 0.4142135f;
    float w = big ? fmaf(0.5f, u, -0.5f) : u;    // (1+u)/2 - 1  in (-0.293, 0.414]
    float z = w * w;
    float p = 7.0376836292e-2f;
    p = fmaf(p, w, -1.1514610310e-1f);
    p = fmaf(p, w,  1.1676998740e-1f);
    p = fmaf(p, w, -1.2420140846e-1f);
    p = fmaf(p, w,  1.4249322787e-1f);
    p = fmaf(p, w, -1.6668057665e-1f);
    p = fmaf(p, w,  2.0000714765e-1f);
    p = fmaf(p, w, -2.4999993993e-1f);
    p = fmaf(p, w,  3.3333331174e-1f);
    float y = fmaf(w * z, p, -0.5f * z);
    float res = w + y;
    return big ? res + 0.69314718056f : res;
}
__device__ __forceinline__ float frcp(float x) {
    float r = __int_as_float(0x7EF311C3 - __float_as_int(x));
    r = r * fmaf(-x, r, 2.0f);
    r = r * fmaf(-x, r, 2.0f);
    r = r * fmaf(-x, r, 2.0f);
    return r;
}

// ================== HMMA machinery ================================================
__device__ __forceinline__ uint32_t s2u(const void* p) {
    uint32_t a;
    asm("{ .reg .u64 t; cvta.to.shared.u64 t, %1; cvt.u32.u64 %0, t; }" : "=r"(a) : "l"(p));
    return a;
}
#define LDSM4(r0, r1, r2, r3, addr) \
    asm volatile("ldmatrix.sync.aligned.m8n8.x4.shared.b16 {%0,%1,%2,%3}, [%4];" \
        : "=r"(r0), "=r"(r1), "=r"(r2), "=r"(r3) : "r"(addr))
#define MMA16816(c, a, b0, b1) \
    asm volatile("mma.sync.aligned.m16n8k16.row.col.f32.bf16.bf16.f32 " \
        "{%0,%1,%2,%3}, {%4,%5,%6,%7}, {%8,%9}, {%0,%1,%2,%3};" \
        : "+f"((c)[0]), "+f"((c)[1]), "+f"((c)[2]), "+f"((c)[3]) \
        : "r"((a)[0]), "r"((a)[1]), "r"((a)[2]), "r"((a)[3]), "r"(b0), "r"(b1))
#define CP_ASYNC16(dst, src) \
    asm volatile("cp.async.cg.shared.global [%0], [%1], 16;" :: "r"(dst), "l"(src))
#define CP_COMMIT()  asm volatile("cp.async.commit_group;" ::: "memory")
#define CP_WAIT1()   asm volatile("cp.async.wait_group 1;" ::: "memory")
#define CP_WAIT0()   asm volatile("cp.async.wait_group 0;" ::: "memory")

#define ROWB   144
#define TILEB  18432            // 128*144
#define BUFB   36864            // A + B

// ================== split-bf16 HMMA GEMM (3-pass, proven) =========================
__global__ void __launch_bounds__(256, 2) hmma_gemm(
    const __nv_bfloat16* __restrict__ Ahi, const __nv_bfloat16* __restrict__ Alo,
    const __nv_bfloat16* __restrict__ Bhi, const __nv_bfloat16* __restrict__ Blo,
    float* __restrict__ C, int N, float alpha)
{
    extern __shared__ char smem[];
    uint32_t sb = s2u(smem);
    int tid = threadIdx.x, lane = tid & 31, wid = tid >> 5;
    int m0 = blockIdx.y << 7, n0 = blockIdx.x << 7;
    int wm = wid & 1, wn = wid >> 1;

    float acc[4][4][4];
#pragma unroll
    for (int i = 0; i < 4; i++)
#pragma unroll
        for (int j = 0; j < 4; j++)
#pragma unroll
            for (int r = 0; r < 4; r++) acc[i][j][r] = 0.0f;

    int lrow  = tid >> 1;
    int lcb   = (tid & 1) * 4;
    uint32_t sa_st = lrow * ROWB + lcb * 16;

    auto stage = [&](int s, int buf) {
        int seg = s >> 3;
        int kk  = (s & 7) << 6;
        const __nv_bfloat16* Ap = (seg == 2) ? Alo : Ahi;
        const __nv_bfloat16* Bp = (seg == 1) ? Blo : Bhi;
        const __nv_bfloat16* ga = Ap + (size_t)(m0 + lrow) * 512 + kk + lcb * 8;
        const __nv_bfloat16* gb = Bp + (size_t)(n0 + lrow) * 512 + kk + lcb * 8;
        uint32_t da = sb + buf * BUFB + sa_st;
        uint32_t db = da + TILEB;
#pragma unroll
        for (int i = 0; i < 4; i++) {
            CP_ASYNC16(da + i * 16, ga + i * 8);
            CP_ASYNC16(db + i * 16, gb + i * 8);
        }
    };

    int r8 = lane & 7, j = lane >> 3;
    uint32_t a_row = (uint32_t)(wm * 64 + (j & 1) * 8 + r8);
    uint32_t a_cb  = (uint32_t)((j >> 1) * 16);
    uint32_t b_row = (uint32_t)(wn * 32 + (j >> 1) * 8 + r8);
    uint32_t b_cb  = (uint32_t)((j & 1) * 16);

    stage(0, 0);
    CP_COMMIT();

    for (int s = 0; s < 24; s++) {
        int buf = s & 1;
        if (s < 23) { stage(s + 1, buf ^ 1); CP_COMMIT(); CP_WAIT1(); }
        else        { CP_WAIT0(); }
        __syncthreads();

        uint32_t abase = sb + buf * BUFB;
        uint32_t bbase = abase + TILEB;
#pragma unroll
        for (int kq = 0; kq < 4; kq++) {
            uint32_t kb = kq * 32;
            uint32_t ra[4][4], rb[2][4];
#pragma unroll
            for (int mt = 0; mt < 4; mt++) {
                uint32_t ad = abase + (a_row + mt * 16) * ROWB + kb + a_cb;
                LDSM4(ra[mt][0], ra[mt][1], ra[mt][2], ra[mt][3], ad);
            }
#pragma unroll
            for (int bt = 0; bt < 2; bt++) {
                uint32_t bd = bbase + (b_row + bt * 16) * ROWB + kb + b_cb;
                LDSM4(rb[bt][0], rb[bt][1], rb[bt][2], rb[bt][3], bd);
            }
#pragma unroll
            for (int mt = 0; mt < 4; mt++)
#pragma unroll
                for (int nt = 0; nt < 4; nt++)
                    MMA16816(acc[mt][nt], ra[mt],
                             rb[nt >> 1][(nt & 1) * 2], rb[nt >> 1][(nt & 1) * 2 + 1]);
        }
        __syncthreads();
    }

    int erow = lane >> 2;
    int ecol = (lane & 3) * 2;
#pragma unroll
    for (int mt = 0; mt < 4; mt++) {
        int row = m0 + wm * 64 + mt * 16 + erow;
#pragma unroll
        for (int nt = 0; nt < 4; nt++) {
            int col = n0 + wn * 32 + nt * 8 + ecol;
            *(float2*)&C[(size_t)row * N + col] =
                make_float2(alpha * acc[mt][nt][0], alpha * acc[mt][nt][1]);
            *(float2*)&C[(size_t)(row + 8) * N + col] =
                make_float2(alpha * acc[mt][nt][2], alpha * acc[mt][nt][3]);
        }
    }
}

// ---------------- prep: split fp32 -> bf16 hi/lo ----------------------------------
__global__ void __launch_bounds__(256) splitx_kernel(
    const float* __restrict__ src, __nv_bfloat16* __restrict__ hi,
    __nv_bfloat16* __restrict__ lo, int n4)
{
    int i = blockIdx.x * 256 + threadIdx.x;
    if (i >= n4) return;
    float4 v = ((const float4*)src)[i];
    float a[4] = {v.x, v.y, v.z, v.w};
    __nv_bfloat16 h[4], l[4];
#pragma unroll
    for (int j = 0; j < 4; j++) {
        h[j] = __float2bfloat16(a[j]);
        l[j] = __float2bfloat16(a[j] - __bfloat162float(h[j]));
    }
    uint2 ph, pl;
    __nv_bfloat162 h01 = {h[0], h[1]}, h23 = {h[2], h[3]};
    __nv_bfloat162 l01 = {l[0], l[1]}, l23 = {l[2], l[3]};
    ph.x = *(uint32_t*)&h01; ph.y = *(uint32_t*)&h23;
    pl.x = *(uint32_t*)&l01; pl.y = *(uint32_t*)&l23;
    *(uint2*)&hi[(size_t)i * 4] = ph;
    *(uint2*)&lo[(size_t)i * 4] = pl;
}

// ---------------- prep: transpose + split + scale W[512,N] -> T[N,512] ------------
__global__ void tsplit_kernel(const float* __restrict__ W,
                              __nv_bfloat16* __restrict__ Th,
                              __nv_bfloat16* __restrict__ Tl, int N, float scale)
{
    __shared__ float t[32][33];
    int n0 = blockIdx.x * 32, k0 = blockIdx.y * 32;
    int lx = threadIdx.x, ly = threadIdx.y;   // 32 x 8
#pragma unroll
    for (int i = 0; i < 4; i++) {
        int k = ly + i * 8;
        t[k][lx] = W[(size_t)(k0 + k) * N + n0 + lx];
    }
    __syncthreads();
#pragma unroll
    for (int i = 0; i < 4; i++) {
        int n = ly + i * 8;
        float v = t[lx][n] * scale;
        __nv_bfloat16 h = __float2bfloat16(v);
        Th[(size_t)(n0 + n) * 512 + k0 + lx] = h;
        Tl[(size_t)(n0 + n) * 512 + k0 + lx] = __float2bfloat16(v - __bfloat162float(h));
    }
}

// ---------------- t1 = x @ Wgk1 : [T,16], W in smem -------------------------------
__global__ void __launch_bounds__(256) t1_kernel(
    const float* __restrict__ x, const float* __restrict__ W)
{
    __shared__ float Ws[512 * 16];
    int tid = threadIdx.x;
    for (int i = tid; i < 512 * 16; i += 256) Ws[i] = W[i];
    __syncthreads();

    int row = blockIdx.x * 64 + (tid >> 2);
    int j0 = (tid & 3) << 2;
    const float4* xr = (const float4*)(x + (size_t)row * 512);
    float a0 = 0, a1 = 0, a2 = 0, a3 = 0;
#pragma unroll 4
    for (int k4 = 0; k4 < 128; k4++) {
        float4 xv = xr[k4];
        int kb = k4 << 2;
        float4 w0 = *(const float4*)&Ws[(kb + 0) * 16 + j0];
        float4 w1 = *(const float4*)&Ws[(kb + 1) * 16 + j0];
        float4 w2 = *(const float4*)&Ws[(kb + 2) * 16 + j0];
        float4 w3 = *(const float4*)&Ws[(kb + 3) * 16 + j0];
        a0 = fmaf(xv.x, w0.x, fmaf(xv.y, w1.x, fmaf(xv.z, w2.x, fmaf(xv.w, w3.x, a0))));
        a1 = fmaf(xv.x, w0.y, fmaf(xv.y, w1.y, fmaf(xv.z, w2.y, fmaf(xv.w, w3.y, a1))));
        a2 = fmaf(xv.x, w0.z, fmaf(xv.y, w1.z, fmaf(xv.z, w2.z, fmaf(xv.w, w3.z, a2))));
        a3 = fmaf(xv.x, w0.w, fmaf(xv.y, w1.w, fmaf(xv.z, w2.w, fmaf(xv.w, w3.w, a3))));
    }
    *(float4*)&t1_buf[(size_t)row * GLR + j0] = make_float4(a0, a1, a2, a3);
}

// ---------------- decay: gk + in-chunk cumsum + exp, all FMA-pipe -----------------
// writes eg = exp(G), einv = exp(-G)  (G = inclusive cumsum of log_sigmoid(s)/16)
__global__ void __launch_bounds__(256) decay_kernel(
    const float* __restrict__ Wgk2, const float* __restrict__ bgk2)
{
    __shared__ float t1s[64][17];
    int gc = blockIdx.x, d = threadIdx.x;
    int t0 = gc << 6;
#pragma unroll
    for (int i = 0; i < 4; i++) {
        int lin = d + (i << 8);
        int r = lin >> 4, c = lin & 15;
        t1s[r][c] = t1_buf[(size_t)(t0 + r) * GLR + c];
    }
    float w[16];
#pragma unroll
    for (int r = 0; r < 16; r++) w[r] = Wgk2[r * DKc + d];
    float b = bgk2[d];
    __syncthreads();

    float G = 0.0f;
    for (int t = 0; t < 64; t++) {
        float s = b;
#pragma unroll
        for (int r = 0; r < 16; r++) s = fmaf(t1s[t][r], w[r], s);
        float u = fexp(-fabsf(s));
        float ls = fminf(s, 0.0f) - flog1p(u);
        G = fmaf(ls, 0.0625f, G);
        size_t idx = (size_t)(t0 + t) * DKc + d;
        eg_buf[idx]   = fexp(G);
        einv_buf[idx] = fexp(-G);
    }
}

// ---------------- per-chunk U = sum_t e^(Glast-Gt) k_t (x) v_t --------------------
__global__ void __launch_bounds__(256, 2) chunkU_kernel()
{
    extern __shared__ float sm[];
    float* kt = sm;            // [64][68]
    float* vt = sm + 4352;     // [64][132]
    int h = blockIdx.x, gc = blockIdx.y;
    int tid = threadIdx.x;
    int tx = tid & 15, ty = tid >> 4;
    int t0 = gc << 6;

#pragma unroll
    for (int i = 0; i < 16; i++) {
        int lin = tid + (i << 8);
        int r = lin >> 6, c = lin & 63;
        float kv   = qkvg_buf[(size_t)(t0 + r) * NQKVG + 256 + h * HK + c];
        float ei   = einv_buf[(size_t)(t0 + r) * DKc + h * HK + c];
        float egl  = eg_buf[(size_t)(t0 + 63) * DKc + h * HK + c];
        kt[r * 68 + c] = kv * (egl * ei);
    }
#pragma unroll
    for (int i = 0; i < 8; i++) {
        int q = tid + (i << 8);
        int r = q >> 5, c4 = (q & 31) << 2;
        *(float4*)&vt[r * 132 + c4] =
            *(const float4*)&qkvg_buf[(size_t)(t0 + r) * NQKVG + 512 + h * HV + c4];
    }
    __syncthreads();

    float acc[4][8];
#pragma unroll
    for (int i = 0; i < 4; i++)
#pragma unroll
        for (int j = 0; j < 8; j++) acc[i][j] = 0.0f;

#pragma unroll 4
    for (int t = 0; t < 64; t++) {
        float4 a0 = *(const float4*)&kt[t * 68 + (ty << 2)];
        float4 b0 = *(const float4*)&vt[t * 132 + (tx << 2)];
        float4 b1 = *(const float4*)&vt[t * 132 + 64 + (tx << 2)];
        float av[4] = {a0.x, a0.y, a0.z, a0.w};
        float bv[8] = {b0.x, b0.y, b0.z, b0.w, b1.x, b1.y, b1.z, b1.w};
#pragma unroll
        for (int i = 0; i < 4; i++)
#pragma unroll
            for (int j = 0; j < 8; j++) acc[i][j] += av[i] * bv[j];
    }

    size_t ub = ((size_t)gc * NH + h) << 13;
#pragma unroll
    for (int i = 0; i < 4; i++) {
        int row = (ty << 2) + i;
        *(float4*)&U_buf[ub + row * 128 + (tx << 2)] =
            make_float4(acc[i][0], acc[i][1], acc[i][2], acc[i][3]);
        *(float4*)&U_buf[ub + row * 128 + 64 + (tx << 2)] =
            make_float4(acc[i][4], acc[i][5], acc[i][6], acc[i][7]);
    }
}

// ---------------- sequential chunk scan, sync-free, v-sliced ----------------------
__global__ void __launch_bounds__(256) scan_kernel()
{
    int h = blockIdx.x, b = blockIdx.y, sl = blockIdx.z;
    int tid = threadIdx.x;
    int k = tid >> 2;
    int voff = (sl << 5) + ((tid & 3) << 3);

    float4 st0 = make_float4(0.f, 0.f, 0.f, 0.f);
    float4 st1 = make_float4(0.f, 0.f, 0.f, 0.f);

#pragma unroll 4
    for (int c = 0; c < 256; c++) {
        int gc = (b << 8) + c;
        float lam = eg_buf[(size_t)((gc << 6) + 63) * DKc + h * HK + k];
        size_t base = (((size_t)gc * NH + h) << 13) + k * 128 + voff;
        float4 u0 = *(const float4*)&U_buf[base];
        float4 u1 = *(const float4*)&U_buf[base + 4];
        *(float4*)&Hi_buf[base]     = st0;
        *(float4*)&Hi_buf[base + 4] = st1;
        st0.x = fmaf(lam, st0.x, u0.x); st0.y = fmaf(lam, st0.y, u0.y);
        st0.z = fmaf(lam, st0.z, u0.z); st0.w = fmaf(lam, st0.w, u0.w);
        st1.x = fmaf(lam, st1.x, u1.x); st1.y = fmaf(lam, st1.y, u1.y);
        st1.z = fmaf(lam, st1.z, u1.z); st1.w = fmaf(lam, st1.w, u1.w);
    }
}

// ---------------- per-chunk output + LN + SiLU (poly), writes bf16 hi/lo ----------
__global__ void __launch_bounds__(256, 2) out_kernel()
{
    extern __shared__ float sm[];
    float* qs = sm;                 // [64][68]
    float* ks = sm + 4352;          // [64][65]
    float* As = sm + 8512;          // [64][68]
    float* vs = sm + 12864;         // [64][132]
    float* os = sm + 4352;          // [64][132] reuse

    int h = blockIdx.x, gc = blockIdx.y;
    int tid = threadIdx.x;
    int tx = tid & 15, ty = tid >> 4;
    int t0 = gc << 6;

#pragma unroll
    for (int i = 0; i < 16; i++) {
        int lin = tid + (i << 8);
        int r = lin >> 6, c = lin & 63;
        size_t gidx = (size_t)(t0 + r) * NQKVG + h * HK + c;
        size_t eidx = (size_t)(t0 + r) * DKc + h * HK + c;
        qs[r * 68 + c] = qkvg_buf[gidx]       * eg_buf[eidx];
        ks[r * 65 + c] = qkvg_buf[gidx + 256] * einv_buf[eidx];
    }
#pragma unroll
    for (int i = 0; i < 8; i++) {
        int q = tid + (i << 8);
        int r = q >> 5, c4 = (q & 31) << 2;
        *(float4*)&vs[r * 132 + c4] =
            *(const float4*)&qkvg_buf[(size_t)(t0 + r) * NQKVG + 512 + h * HV + c4];
    }
    __syncthreads();

    {
        int tt = (tid >> 4) << 2;
        int ss = (tid & 15) << 2;
        float a[4][4];
#pragma unroll
        for (int i = 0; i < 4; i++)
#pragma unroll
            for (int j = 0; j < 4; j++) a[i][j] = 0.0f;
#pragma unroll 4
        for (int k = 0; k < 64; k++) {
            float qv[4], kv[4];
#pragma unroll
            for (int i = 0; i < 4; i++) { qv[i] = qs[(tt + i) * 68 + k]; kv[i] = ks[(ss + i) * 65 + k]; }
#pragma unroll
            for (int i = 0; i < 4; i++)
#pragma unroll
                for (int j = 0; j < 4; j++) a[i][j] += qv[i] * kv[j];
        }
#pragma unroll
        for (int i = 0; i < 4; i++)
#pragma unroll
            for (int j = 0; j < 4; j++)
                As[(tt + i) * 68 + ss + j] = (ss + j <= tt + i) ? a[i][j] : 0.0f;
    }
    __syncthreads();

    float acc[4][8];
#pragma unroll
    for (int i = 0; i < 4; i++)
#pragma unroll
        for (int j = 0; j < 8; j++) acc[i][j] = 0.0f;

#pragma unroll 4
    for (int s = 0; s < 64; s++) {
        float4 b0 = *(const float4*)&vs[s * 132 + (tx << 2)];
        float4 b1 = *(const float4*)&vs[s * 132 + 64 + (tx << 2)];
        float av[4];
#pragma unroll
        for (int i = 0; i < 4; i++) av[i] = As[((ty << 2) + i) * 68 + s];
        float bv[8] = {b0.x, b0.y, b0.z, b0.w, b1.x, b1.y, b1.z, b1.w};
#pragma unroll
        for (int i = 0; i < 4; i++)
#pragma unroll
            for (int j = 0; j < 8; j++) acc[i][j] += av[i] * bv[j];
    }
    __syncthreads();

    {
        size_t hb = ((size_t)gc * NH + h) << 13;
#pragma unroll
        for (int i = 0; i < 8; i++) {
            int q = tid + (i << 8);
            int r = q >> 5, c4 = (q & 31) << 2;
            *(float4*)&vs[r * 132 + c4] = *(const float4*)&Hi_buf[hb + r * 128 + c4];
        }
    }
    __syncthreads();

#pragma unroll 4
    for (int k = 0; k < 64; k++) {
        float4 b0 = *(const float4*)&vs[k * 132 + (tx << 2)];
        float4 b1 = *(const float4*)&vs[k * 132 + 64 + (tx << 2)];
        float av[4];
#pragma unroll
        for (int i = 0; i < 4; i++) av[i] = qs[((ty << 2) + i) * 68 + k];
        float bv[8] = {b0.x, b0.y, b0.z, b0.w, b1.x, b1.y, b1.z, b1.w};
#pragma unroll
        for (int i = 0; i < 4; i++)
#pragma unroll
            for (int j = 0; j < 8; j++) acc[i][j] += av[i] * bv[j];
    }
    __syncthreads();

#pragma unroll
    for (int i = 0; i < 4; i++) {
        int row = (ty << 2) + i;
        *(float4*)&os[row * 132 + (tx << 2)] =
            make_float4(acc[i][0], acc[i][1], acc[i][2], acc[i][3]);
        *(float4*)&os[row * 132 + 64 + (tx << 2)] =
            make_float4(acc[i][4], acc[i][5], acc[i][6], acc[i][7]);
    }
    __syncthreads();

    int t = tid >> 2;
    int jsub = tid & 3;
    float o[32];
#pragma unroll
    for (int jj = 0; jj < 8; jj++) {
        float4 v4 = *(const float4*)&os[t * 132 + (jsub << 5) + (jj << 2)];
        o[jj*4+0] = v4.x; o[jj*4+1] = v4.y; o[jj*4+2] = v4.z; o[jj*4+3] = v4.w;
    }
    float s1 = 0.0f;
#pragma unroll
    for (int jj = 0; jj < 32; jj++) s1 += o[jj];
    s1 += __shfl_xor_sync(0xffffffffu, s1, 1);
    s1 += __shfl_xor_sync(0xffffffffu, s1, 2);
    float mu = s1 * (1.0f / 128.0f);
    float s2 = 0.0f;
#pragma unroll
    for (int jj = 0; jj < 32; jj++) { float d = o[jj] - mu; s2 += d * d; }
    s2 += __shfl_xor_sync(0xffffffffu, s2, 1);
    s2 += __shfl_xor_sync(0xffffffffu, s2, 2);
    float rstd = rsqrtf(s2 * (1.0f / 128.0f) + 1e-5f);

    size_t orow = (size_t)(t0 + t) * DVc + h * HV + (jsub << 5);
    size_t grow = (size_t)(t0 + t) * NQKVG + 1024 + h * HV + (jsub << 5);
#pragma unroll
    for (int jj = 0; jj < 32; jj++) {
        float gg = qkvg_buf[grow + jj];
        float sg = gg * frcp(1.0f + fexp(-gg));            // silu, FMA-pipe only
        float val = (o[jj] - mu) * rstd * sg;
        __nv_bfloat16 hb = __float2bfloat16(val);
        ohi_buf[orow + jj] = hb;
        olo_buf[orow + jj] = __float2bfloat16(val - __bfloat162float(hb));
    }
}

// ---------------------------------------------------------------------------------
extern "C" void kernel_launch(void* const* d_in, const int* in_sizes, int n_in,
                              void* d_out, int out_size)
{
    const float* x    = (const float*)d_in[0];
    const float* Wq   = (const float*)d_in[1];
    const float* Wk   = (const float*)d_in[2];
    const float* Wv   = (const float*)d_in[3];
    const float* Wg   = (const float*)d_in[4];
    const float* Wgk1 = (const float*)d_in[5];
    const float* Wgk2 = (const float*)d_in[6];
    const float* bgk2 = (const float*)d_in[7];
    const float* Wo   = (const float*)d_in[8];
    float* out = (float*)d_out;
    (void)in_sizes; (void)n_in; (void)out_size;

    void *pqkvg, *pxh, *pxl, *poh, *pol, *pwch, *pwcl, *pwoh, *pwol;
    cudaGetSymbolAddress(&pqkvg, qkvg_buf);
    cudaGetSymbolAddress(&pxh, xhi_buf);
    cudaGetSymbolAddress(&pxl, xlo_buf);
    cudaGetSymbolAddress(&poh, ohi_buf);
    cudaGetSymbolAddress(&pol, olo_buf);
    cudaGetSymbolAddress(&pwch, wcat_hi);
    cudaGetSymbolAddress(&pwcl, wcat_lo);
    cudaGetSymbolAddress(&pwoh, wo_hi);
    cudaGetSymbolAddress(&pwol, wo_lo);

    cudaFuncSetAttribute(hmma_gemm,     cudaFuncAttributeMaxDynamicSharedMemorySize, 2 * BUFB);
    cudaFuncSetAttribute(out_kernel,    cudaFuncAttributeMaxDynamicSharedMemorySize, 85248);
    cudaFuncSetAttribute(chunkU_kernel, cudaFuncAttributeMaxDynamicSharedMemorySize, 51200);

    typedef __nv_bfloat16* bfp;
    typedef const __nv_bfloat16* cbf;
    bfp wch = (bfp)pwch, wcl = (bfp)pwcl;

    // prep
    splitx_kernel<<<T_TOK * D_MODEL / 4 / 256, 256>>>(x, (bfp)pxh, (bfp)pxl,
                                                      T_TOK * D_MODEL / 4);
    tsplit_kernel<<<dim3(8, 16),  dim3(32, 8)>>>(Wq, wch,               wcl,               DKc, 0.125f);
    tsplit_kernel<<<dim3(8, 16),  dim3(32, 8)>>>(Wk, wch + 256 * 512,   wcl + 256 * 512,   DKc, 1.0f);
    tsplit_kernel<<<dim3(16, 16), dim3(32, 8)>>>(Wv, wch + 512 * 512,   wcl + 512 * 512,   DVc, 1.0f);
    tsplit_kernel<<<dim3(16, 16), dim3(32, 8)>>>(Wg, wch + 1024 * 512,  wcl + 1024 * 512,  DVc, 1.0f);
    tsplit_kernel<<<dim3(16, 16), dim3(32, 8)>>>(Wo, (bfp)pwoh,         (bfp)pwol,         D_MODEL, 1.0f);

    t1_kernel<<<T_TOK / 64, 256>>>(x, Wgk1);
    decay_kernel<<<NCHUNK, 256>>>(Wgk2, bgk2);

    // fused q|k|v|g projection: C[T,1536]
    hmma_gemm<<<dim3(NQKVG / 128, T_TOK / 128), 256, 2 * BUFB>>>(
        (cbf)pxh, (cbf)pxl, (cbf)pwch, (cbf)pwcl, (float*)pqkvg, NQKVG, 1.0f);

    chunkU_kernel<<<dim3(NH, NCHUNK), 256, 51200>>>();
    scan_kernel<<<dim3(NH, 2, 4), 256>>>();
    out_kernel<<<dim3(NH, NCHUNK), 256, 85248>>>();

    hmma_gemm<<<dim3(D_MODEL / 128, T_TOK / 128), 256, 2 * BUFB>>>(
        (cbf)poh, (cbf)pol, (cbf)pwoh, (cbf)pwol, out, D_MODEL, 1.0f);
}

// round 10
// speedup vs baseline: 2.3374x; 1.0307x over previous
#include <cuda_runtime.h>
#include <cuda_bf16.h>
#include <cstdint>
#include <math.h>

#define T_TOK   32768      // B*S
#define D_MODEL 512
#define DKc     256
#define DVc     512
#define NH      4
#define HK      64
#define HV      128
#define CH      64
#define NCHUNK  512
#define GLR     16
#define NQKVG   1536       // 256 q + 256 k + 512 v + 512 g

// ---------------- scratch (device globals) ----------------------------------------
__device__ __align__(16) float qkvg_buf[(size_t)T_TOK*NQKVG];
__device__ __align__(16) float t1_buf [T_TOK*GLR];
__device__ __align__(16) float eg_buf [T_TOK*DKc];
__device__ __align__(16) float einv_buf[T_TOK*DKc];
__device__ __align__(16) float U_buf [(size_t)NCHUNK*NH*HK*HV];
__device__ __align__(16) float Hi_buf[(size_t)NCHUNK*NH*HK*HV];

__device__ __align__(16) __nv_bfloat16 xhi_buf[T_TOK*D_MODEL];
__device__ __align__(16) __nv_bfloat16 xlo_buf[T_TOK*D_MODEL];
__device__ __align__(16) __nv_bfloat16 ohi_buf[T_TOK*DVc];
__device__ __align__(16) __nv_bfloat16 olo_buf[T_TOK*DVc];
__device__ __align__(16) __nv_bfloat16 wcat_hi[NQKVG*D_MODEL], wcat_lo[NQKVG*D_MODEL];
__device__ __align__(16) __nv_bfloat16 wo_hi[D_MODEL*DVc],     wo_lo[D_MODEL*DVc];

// ================== FMA-only transcendentals (avoid the slow MUFU pipe) ===========
__device__ __forceinline__ float fexp(float x) {
    float n = rintf(x * 1.4426950408889634f);
    float r = fmaf(n, -0.693359375f, x);
    r = fmaf(n, 2.12194440054690583e-4f, r);
    float p = 1.3888888888e-3f;
    p = fmaf(p, r, 8.3333333333e-3f);
    p = fmaf(p, r, 4.1666666666e-2f);
    p = fmaf(p, r, 1.6666666666e-1f);
    p = fmaf(p, r, 0.5f);
    p = fmaf(p, r, 1.0f);
    p = fmaf(p, r, 1.0f);
    int ni = (int)n;
    return p * __int_as_float((ni + 127) << 23);
}
// log(1+u) for u in (0, 1]
__device__ __forceinline__ float flog1p(float u) {
    bool big = u > 0.4142135f;
    float w = big ? fmaf(0.5f, u, -0.5f) : u;    // (1+u)/2 - 1  in (-0.293, 0.414]
    float z = w * w;
    float p = 7.0376836292e-2f;
    p = fmaf(p, w, -1.1514610310e-1f);
    p = fmaf(p, w,  1.1676998740e-1f);
    p = fmaf(p, w, -1.2420140846e-1f);
    p = fmaf(p, w,  1.4249322787e-1f);
    p = fmaf(p, w, -1.6668057665e-1f);
    p = fmaf(p, w,  2.0000714765e-1f);
    p = fmaf(p, w, -2.4999993993e-1f);
    p = fmaf(p, w,  3.3333331174e-1f);
    float y = fmaf(w * z, p, -0.5f * z);
    float res = w + y;
    return big ? res + 0.69314718056f : res;
}
__device__ __forceinline__ float frcp(float x) {
    float r = __int_as_float(0x7EF311C3 - __float_as_int(x));
    r = r * fmaf(-x, r, 2.0f);
    r = r * fmaf(-x, r, 2.0f);
    r = r * fmaf(-x, r, 2.0f);
    return r;
}

// ================== HMMA machinery ================================================
__device__ __forceinline__ uint32_t s2u(const void* p) {
    uint32_t a;
    asm("{ .reg .u64 t; cvta.to.shared.u64 t, %1; cvt.u32.u64 %0, t; }" : "=r"(a) : "l"(p));
    return a;
}
#define LDSM4(r0, r1, r2, r3, addr) \
    asm volatile("ldmatrix.sync.aligned.m8n8.x4.shared.b16 {%0,%1,%2,%3}, [%4];" \
        : "=r"(r0), "=r"(r1), "=r"(r2), "=r"(r3) : "r"(addr))
#define MMA16816(c, a, b0, b1) \
    asm volatile("mma.sync.aligned.m16n8k16.row.col.f32.bf16.bf16.f32 " \
        "{%0,%1,%2,%3}, {%4,%5,%6,%7}, {%8,%9}, {%0,%1,%2,%3};" \
        : "+f"((c)[0]), "+f"((c)[1]), "+f"((c)[2]), "+f"((c)[3]) \
        : "r"((a)[0]), "r"((a)[1]), "r"((a)[2]), "r"((a)[3]), "r"(b0), "r"(b1))
#define CP_ASYNC16(dst, src) \
    asm volatile("cp.async.cg.shared.global [%0], [%1], 16;" :: "r"(dst), "l"(src))
#define CP_COMMIT()  asm volatile("cp.async.commit_group;" ::: "memory")
#define CP_WAIT1()   asm volatile("cp.async.wait_group 1;" ::: "memory")
#define CP_WAIT0()   asm volatile("cp.async.wait_group 0;" ::: "memory")

#define ROWB   144
#define TILEB  18432            // 128*144
#define BUFB   36864            // A + B

// ================== split-bf16 HMMA GEMM (3-pass, proven) =========================
__global__ void __launch_bounds__(256, 2) hmma_gemm(
    const __nv_bfloat16* __restrict__ Ahi, const __nv_bfloat16* __restrict__ Alo,
    const __nv_bfloat16* __restrict__ Bhi, const __nv_bfloat16* __restrict__ Blo,
    float* __restrict__ C, int N, float alpha)
{
    extern __shared__ char smem[];
    uint32_t sb = s2u(smem);
    int tid = threadIdx.x, lane = tid & 31, wid = tid >> 5;
    int m0 = blockIdx.y << 7, n0 = blockIdx.x << 7;
    int wm = wid & 1, wn = wid >> 1;

    float acc[4][4][4];
#pragma unroll
    for (int i = 0; i < 4; i++)
#pragma unroll
        for (int j = 0; j < 4; j++)
#pragma unroll
            for (int r = 0; r < 4; r++) acc[i][j][r] = 0.0f;

    int lrow  = tid >> 1;
    int lcb   = (tid & 1) * 4;
    uint32_t sa_st = lrow * ROWB + lcb * 16;

    auto stage = [&](int s, int buf) {
        int seg = s >> 3;
        int kk  = (s & 7) << 6;
        const __nv_bfloat16* Ap = (seg == 2) ? Alo : Ahi;
        const __nv_bfloat16* Bp = (seg == 1) ? Blo : Bhi;
        const __nv_bfloat16* ga = Ap + (size_t)(m0 + lrow) * 512 + kk + lcb * 8;
        const __nv_bfloat16* gb = Bp + (size_t)(n0 + lrow) * 512 + kk + lcb * 8;
        uint32_t da = sb + buf * BUFB + sa_st;
        uint32_t db = da + TILEB;
#pragma unroll
        for (int i = 0; i < 4; i++) {
            CP_ASYNC16(da + i * 16, ga + i * 8);
            CP_ASYNC16(db + i * 16, gb + i * 8);
        }
    };

    int r8 = lane & 7, j = lane >> 3;
    uint32_t a_row = (uint32_t)(wm * 64 + (j & 1) * 8 + r8);
    uint32_t a_cb  = (uint32_t)((j >> 1) * 16);
    uint32_t b_row = (uint32_t)(wn * 32 + (j >> 1) * 8 + r8);
    uint32_t b_cb  = (uint32_t)((j & 1) * 16);

    stage(0, 0);
    CP_COMMIT();

    for (int s = 0; s < 24; s++) {
        int buf = s & 1;
        if (s < 23) { stage(s + 1, buf ^ 1); CP_COMMIT(); CP_WAIT1(); }
        else        { CP_WAIT0(); }
        __syncthreads();

        uint32_t abase = sb + buf * BUFB;
        uint32_t bbase = abase + TILEB;
#pragma unroll
        for (int kq = 0; kq < 4; kq++) {
            uint32_t kb = kq * 32;
            uint32_t ra[4][4], rb[2][4];
#pragma unroll
            for (int mt = 0; mt < 4; mt++) {
                uint32_t ad = abase + (a_row + mt * 16) * ROWB + kb + a_cb;
                LDSM4(ra[mt][0], ra[mt][1], ra[mt][2], ra[mt][3], ad);
            }
#pragma unroll
            for (int bt = 0; bt < 2; bt++) {
                uint32_t bd = bbase + (b_row + bt * 16) * ROWB + kb + b_cb;
                LDSM4(rb[bt][0], rb[bt][1], rb[bt][2], rb[bt][3], bd);
            }
#pragma unroll
            for (int mt = 0; mt < 4; mt++)
#pragma unroll
                for (int nt = 0; nt < 4; nt++)
                    MMA16816(acc[mt][nt], ra[mt],
                             rb[nt >> 1][(nt & 1) * 2], rb[nt >> 1][(nt & 1) * 2 + 1]);
        }
        __syncthreads();
    }

    int erow = lane >> 2;
    int ecol = (lane & 3) * 2;
#pragma unroll
    for (int mt = 0; mt < 4; mt++) {
        int row = m0 + wm * 64 + mt * 16 + erow;
#pragma unroll
        for (int nt = 0; nt < 4; nt++) {
            int col = n0 + wn * 32 + nt * 8 + ecol;
            *(float2*)&C[(size_t)row * N + col] =
                make_float2(alpha * acc[mt][nt][0], alpha * acc[mt][nt][1]);
            *(float2*)&C[(size_t)(row + 8) * N + col] =
                make_float2(alpha * acc[mt][nt][2], alpha * acc[mt][nt][3]);
        }
    }
}

// ---------------- prep: split fp32 -> bf16 hi/lo ----------------------------------
__global__ void __launch_bounds__(256) splitx_kernel(
    const float* __restrict__ src, __nv_bfloat16* __restrict__ hi,
    __nv_bfloat16* __restrict__ lo, int n4)
{
    int i = blockIdx.x * 256 + threadIdx.x;
    if (i >= n4) return;
    float4 v = ((const float4*)src)[i];
    float a[4] = {v.x, v.y, v.z, v.w};
    __nv_bfloat16 h[4], l[4];
#pragma unroll
    for (int j = 0; j < 4; j++) {
        h[j] = __float2bfloat16(a[j]);
        l[j] = __float2bfloat16(a[j] - __bfloat162float(h[j]));
    }
    uint2 ph, pl;
    __nv_bfloat162 h01 = {h[0], h[1]}, h23 = {h[2], h[3]};
    __nv_bfloat162 l01 = {l[0], l[1]}, l23 = {l[2], l[3]};
    ph.x = *(uint32_t*)&h01; ph.y = *(uint32_t*)&h23;
    pl.x = *(uint32_t*)&l01; pl.y = *(uint32_t*)&l23;
    *(uint2*)&hi[(size_t)i * 4] = ph;
    *(uint2*)&lo[(size_t)i * 4] = pl;
}

// ---------------- prep: transpose + split + scale W[512,N] -> T[N,512] ------------
__global__ void tsplit_kernel(const float* __restrict__ W,
                              __nv_bfloat16* __restrict__ Th,
                              __nv_bfloat16* __restrict__ Tl, int N, float scale)
{
    __shared__ float t[32][33];
    int n0 = blockIdx.x * 32, k0 = blockIdx.y * 32;
    int lx = threadIdx.x, ly = threadIdx.y;   // 32 x 8
#pragma unroll
    for (int i = 0; i < 4; i++) {
        int k = ly + i * 8;
        t[k][lx] = W[(size_t)(k0 + k) * N + n0 + lx];
    }
    __syncthreads();
#pragma unroll
    for (int i = 0; i < 4; i++) {
        int n = ly + i * 8;
        float v = t[lx][n] * scale;
        __nv_bfloat16 h = __float2bfloat16(v);
        Th[(size_t)(n0 + n) * 512 + k0 + lx] = h;
        Tl[(size_t)(n0 + n) * 512 + k0 + lx] = __float2bfloat16(v - __bfloat162float(h));
    }
}

// ---------------- t1 = x @ Wgk1 : [T,16], W in smem -------------------------------
__global__ void __launch_bounds__(256) t1_kernel(
    const float* __restrict__ x, const float* __restrict__ W)
{
    __shared__ float Ws[512 * 16];
    int tid = threadIdx.x;
    for (int i = tid; i < 512 * 16; i += 256) Ws[i] = W[i];
    __syncthreads();

    int row = blockIdx.x * 64 + (tid >> 2);
    int j0 = (tid & 3) << 2;
    const float4* xr = (const float4*)(x + (size_t)row * 512);
    float a0 = 0, a1 = 0, a2 = 0, a3 = 0;
#pragma unroll 4
    for (int k4 = 0; k4 < 128; k4++) {
        float4 xv = xr[k4];
        int kb = k4 << 2;
        float4 w0 = *(const float4*)&Ws[(kb + 0) * 16 + j0];
        float4 w1 = *(const float4*)&Ws[(kb + 1) * 16 + j0];
        float4 w2 = *(const float4*)&Ws[(kb + 2) * 16 + j0];
        float4 w3 = *(const float4*)&Ws[(kb + 3) * 16 + j0];
        a0 = fmaf(xv.x, w0.x, fmaf(xv.y, w1.x, fmaf(xv.z, w2.x, fmaf(xv.w, w3.x, a0))));
        a1 = fmaf(xv.x, w0.y, fmaf(xv.y, w1.y, fmaf(xv.z, w2.y, fmaf(xv.w, w3.y, a1))));
        a2 = fmaf(xv.x, w0.z, fmaf(xv.y, w1.z, fmaf(xv.z, w2.z, fmaf(xv.w, w3.z, a2))));
        a3 = fmaf(xv.x, w0.w, fmaf(xv.y, w1.w, fmaf(xv.z, w2.w, fmaf(xv.w, w3.w, a3))));
    }
    *(float4*)&t1_buf[(size_t)row * GLR + j0] = make_float4(a0, a1, a2, a3);
}

// ---------------- decay: gk + in-chunk cumsum + exp, all FMA-pipe -----------------
__global__ void __launch_bounds__(256) decay_kernel(
    const float* __restrict__ Wgk2, const float* __restrict__ bgk2)
{
    __shared__ float t1s[64][17];
    int gc = blockIdx.x, d = threadIdx.x;
    int t0 = gc << 6;
#pragma unroll
    for (int i = 0; i < 4; i++) {
        int lin = d + (i << 8);
        int r = lin >> 4, c = lin & 15;
        t1s[r][c] = t1_buf[(size_t)(t0 + r) * GLR + c];
    }
    float w[16];
#pragma unroll
    for (int r = 0; r < 16; r++) w[r] = Wgk2[r * DKc + d];
    float b = bgk2[d];
    __syncthreads();

    float G = 0.0f;
    for (int t = 0; t < 64; t++) {
        float s = b;
#pragma unroll
        for (int r = 0; r < 16; r++) s = fmaf(t1s[t][r], w[r], s);
        float u = fexp(-fabsf(s));
        float ls = fminf(s, 0.0f) - flog1p(u);
        G = fmaf(ls, 0.0625f, G);
        size_t idx = (size_t)(t0 + t) * DKc + d;
        eg_buf[idx]   = fexp(G);
        einv_buf[idx] = fexp(-G);
    }
}

// ---------------- per-chunk U = sum_t e^(Glast-Gt) k_t (x) v_t --------------------
__global__ void __launch_bounds__(256, 2) chunkU_kernel()
{
    extern __shared__ float sm[];
    float* kt = sm;            // [64][68]
    float* vt = sm + 4352;     // [64][132]
    int h = blockIdx.x, gc = blockIdx.y;
    int tid = threadIdx.x;
    int tx = tid & 15, ty = tid >> 4;
    int t0 = gc << 6;

#pragma unroll
    for (int i = 0; i < 16; i++) {
        int lin = tid + (i << 8);
        int r = lin >> 6, c = lin & 63;
        float kv   = qkvg_buf[(size_t)(t0 + r) * NQKVG + 256 + h * HK + c];
        float ei   = einv_buf[(size_t)(t0 + r) * DKc + h * HK + c];
        float egl  = eg_buf[(size_t)(t0 + 63) * DKc + h * HK + c];
        kt[r * 68 + c] = kv * (egl * ei);
    }
#pragma unroll
    for (int i = 0; i < 8; i++) {
        int q = tid + (i << 8);
        int r = q >> 5, c4 = (q & 31) << 2;
        *(float4*)&vt[r * 132 + c4] =
            *(const float4*)&qkvg_buf[(size_t)(t0 + r) * NQKVG + 512 + h * HV + c4];
    }
    __syncthreads();

    float acc[4][8];
#pragma unroll
    for (int i = 0; i < 4; i++)
#pragma unroll
        for (int j = 0; j < 8; j++) acc[i][j] = 0.0f;

#pragma unroll 4
    for (int t = 0; t < 64; t++) {
        float4 a0 = *(const float4*)&kt[t * 68 + (ty << 2)];
        float4 b0 = *(const float4*)&vt[t * 132 + (tx << 2)];
        float4 b1 = *(const float4*)&vt[t * 132 + 64 + (tx << 2)];
        float av[4] = {a0.x, a0.y, a0.z, a0.w};
        float bv[8] = {b0.x, b0.y, b0.z, b0.w, b1.x, b1.y, b1.z, b1.w};
#pragma unroll
        for (int i = 0; i < 4; i++)
#pragma unroll
            for (int j = 0; j < 8; j++) acc[i][j] += av[i] * bv[j];
    }

    size_t ub = ((size_t)gc * NH + h) << 13;
#pragma unroll
    for (int i = 0; i < 4; i++) {
        int row = (ty << 2) + i;
        *(float4*)&U_buf[ub + row * 128 + (tx << 2)] =
            make_float4(acc[i][0], acc[i][1], acc[i][2], acc[i][3]);
        *(float4*)&U_buf[ub + row * 128 + 64 + (tx << 2)] =
            make_float4(acc[i][4], acc[i][5], acc[i][6], acc[i][7]);
    }
}

// ---------------- sequential chunk scan, sync-free, 16 v-slices -------------------
__global__ void __launch_bounds__(256) scan_kernel()
{
    int h = blockIdx.x, b = blockIdx.y, sl = blockIdx.z;   // sl in 0..15
    int tid = threadIdx.x;
    int k = tid >> 2;                       // 0..63 (key dim)
    int voff = (sl << 3) + ((tid & 3) << 1);   // 8-col slice, 2 floats/thread

    float2 st = make_float2(0.f, 0.f);

#pragma unroll 4
    for (int c = 0; c < 256; c++) {
        int gc = (b << 8) + c;
        float lam = eg_buf[(size_t)((gc << 6) + 63) * DKc + h * HK + k];
        size_t base = (((size_t)gc * NH + h) << 13) + k * 128 + voff;
        float2 u = *(const float2*)&U_buf[base];
        *(float2*)&Hi_buf[base] = st;
        st.x = fmaf(lam, st.x, u.x);
        st.y = fmaf(lam, st.y, u.y);
    }
}

// ---------------- per-chunk output + shuffle-LN + SiLU, writes bf16 hi/lo ---------
__global__ void __launch_bounds__(256, 2) out_kernel()
{
    extern __shared__ float sm[];
    float* qs = sm;                 // [64][68]
    float* ks = sm + 4352;          // [64][65]
    float* As = sm + 8512;          // [64][68]
    float* vs = sm + 12864;         // [64][132]

    int h = blockIdx.x, gc = blockIdx.y;
    int tid = threadIdx.x;
    int tx = tid & 15, ty = tid >> 4;
    int t0 = gc << 6;

#pragma unroll
    for (int i = 0; i < 16; i++) {
        int lin = tid + (i << 8);
        int r = lin >> 6, c = lin & 63;
        size_t gidx = (size_t)(t0 + r) * NQKVG + h * HK + c;
        size_t eidx = (size_t)(t0 + r) * DKc + h * HK + c;
        qs[r * 68 + c] = qkvg_buf[gidx]       * eg_buf[eidx];
        ks[r * 65 + c] = qkvg_buf[gidx + 256] * einv_buf[eidx];
    }
#pragma unroll
    for (int i = 0; i < 8; i++) {
        int q = tid + (i << 8);
        int r = q >> 5, c4 = (q & 31) << 2;
        *(float4*)&vs[r * 132 + c4] =
            *(const float4*)&qkvg_buf[(size_t)(t0 + r) * NQKVG + 512 + h * HV + c4];
    }
    __syncthreads();

    {
        int tt = (tid >> 4) << 2;
        int ss = (tid & 15) << 2;
        float a[4][4];
#pragma unroll
        for (int i = 0; i < 4; i++)
#pragma unroll
            for (int j = 0; j < 4; j++) a[i][j] = 0.0f;
#pragma unroll 4
        for (int k = 0; k < 64; k++) {
            float qv[4], kv[4];
#pragma unroll
            for (int i = 0; i < 4; i++) { qv[i] = qs[(tt + i) * 68 + k]; kv[i] = ks[(ss + i) * 65 + k]; }
#pragma unroll
            for (int i = 0; i < 4; i++)
#pragma unroll
                for (int j = 0; j < 4; j++) a[i][j] += qv[i] * kv[j];
        }
#pragma unroll
        for (int i = 0; i < 4; i++)
#pragma unroll
            for (int j = 0; j < 4; j++)
                As[(tt + i) * 68 + ss + j] = (ss + j <= tt + i) ? a[i][j] : 0.0f;
    }
    __syncthreads();

    float acc[4][8];
#pragma unroll
    for (int i = 0; i < 4; i++)
#pragma unroll
        for (int j = 0; j < 8; j++) acc[i][j] = 0.0f;

#pragma unroll 4
    for (int s = 0; s < 64; s++) {
        float4 b0 = *(const float4*)&vs[s * 132 + (tx << 2)];
        float4 b1 = *(const float4*)&vs[s * 132 + 64 + (tx << 2)];
        float av[4];
#pragma unroll
        for (int i = 0; i < 4; i++) av[i] = As[((ty << 2) + i) * 68 + s];
        float bv[8] = {b0.x, b0.y, b0.z, b0.w, b1.x, b1.y, b1.z, b1.w};
#pragma unroll
        for (int i = 0; i < 4; i++)
#pragma unroll
            for (int j = 0; j < 8; j++) acc[i][j] += av[i] * bv[j];
    }
    __syncthreads();

    {
        size_t hb = ((size_t)gc * NH + h) << 13;
#pragma unroll
        for (int i = 0; i < 8; i++) {
            int q = tid + (i << 8);
            int r = q >> 5, c4 = (q & 31) << 2;
            *(float4*)&vs[r * 132 + c4] = *(const float4*)&Hi_buf[hb + r * 128 + c4];
        }
    }
    __syncthreads();

#pragma unroll 4
    for (int k = 0; k < 64; k++) {
        float4 b0 = *(const float4*)&vs[k * 132 + (tx << 2)];
        float4 b1 = *(const float4*)&vs[k * 132 + 64 + (tx << 2)];
        float av[4];
#pragma unroll
        for (int i = 0; i < 4; i++) av[i] = qs[((ty << 2) + i) * 68 + k];
        float bv[8] = {b0.x, b0.y, b0.z, b0.w, b1.x, b1.y, b1.z, b1.w};
#pragma unroll
        for (int i = 0; i < 4; i++)
#pragma unroll
            for (int j = 0; j < 8; j++) acc[i][j] += av[i] * bv[j];
    }

    // shuffle-LN epilogue: row (ty*4+i) cols spread over 16 tx lanes (8 cols each).
    // xor offsets 1,2,4,8 stay within the 16-lane tx group of the warp.
#pragma unroll
    for (int i = 0; i < 4; i++) {
        float s1 = 0.0f;
#pragma unroll
        for (int j = 0; j < 8; j++) s1 += acc[i][j];
        s1 += __shfl_xor_sync(0xffffffffu, s1, 1);
        s1 += __shfl_xor_sync(0xffffffffu, s1, 2);
        s1 += __shfl_xor_sync(0xffffffffu, s1, 4);
        s1 += __shfl_xor_sync(0xffffffffu, s1, 8);
        float mu = s1 * (1.0f / 128.0f);
        float s2 = 0.0f;
#pragma unroll
        for (int j = 0; j < 8; j++) { float d = acc[i][j] - mu; s2 += d * d; }
        s2 += __shfl_xor_sync(0xffffffffu, s2, 1);
        s2 += __shfl_xor_sync(0xffffffffu, s2, 2);
        s2 += __shfl_xor_sync(0xffffffffu, s2, 4);
        s2 += __shfl_xor_sync(0xffffffffu, s2, 8);
        float rstd = rsqrtf(s2 * (1.0f / 128.0f) + 1e-5f);

        int row = (ty << 2) + i;
        size_t rbase = (size_t)(t0 + row);
        size_t gb0 = rbase * NQKVG + 1024 + h * HV + (tx << 2);
        size_t ob0 = rbase * DVc + h * HV + (tx << 2);

#pragma unroll
        for (int half = 0; half < 2; half++) {
            float4 g4 = *(const float4*)&qkvg_buf[gb0 + half * 64];
            float gv[4] = {g4.x, g4.y, g4.z, g4.w};
            __nv_bfloat16 hh[4], ll[4];
#pragma unroll
            for (int j = 0; j < 4; j++) {
                float gg = gv[j];
                float sg = gg * frcp(1.0f + fexp(-gg));
                float val = (acc[i][half * 4 + j] - mu) * rstd * sg;
                hh[j] = __float2bfloat16(val);
                ll[j] = __float2bfloat16(val - __bfloat162float(hh[j]));
            }
            __nv_bfloat162 h01 = {hh[0], hh[1]}, h23 = {hh[2], hh[3]};
            __nv_bfloat162 l01 = {ll[0], ll[1]}, l23 = {ll[2], ll[3]};
            uint2 ph, pl;
            ph.x = *(uint32_t*)&h01; ph.y = *(uint32_t*)&h23;
            pl.x = *(uint32_t*)&l01; pl.y = *(uint32_t*)&l23;
            *(uint2*)&ohi_buf[ob0 + half * 64] = ph;
            *(uint2*)&olo_buf[ob0 + half * 64] = pl;
        }
    }
}

// ---------------------------------------------------------------------------------
extern "C" void kernel_launch(void* const* d_in, const int* in_sizes, int n_in,
                              void* d_out, int out_size)
{
    const float* x    = (const float*)d_in[0];
    const float* Wq   = (const float*)d_in[1];
    const float* Wk   = (const float*)d_in[2];
    const float* Wv   = (const float*)d_in[3];
    const float* Wg   = (const float*)d_in[4];
    const float* Wgk1 = (const float*)d_in[5];
    const float* Wgk2 = (const float*)d_in[6];
    const float* bgk2 = (const float*)d_in[7];
    const float* Wo   = (const float*)d_in[8];
    float* out = (float*)d_out;
    (void)in_sizes; (void)n_in; (void)out_size;

    void *pqkvg, *pxh, *pxl, *poh, *pol, *pwch, *pwcl, *pwoh, *pwol;
    cudaGetSymbolAddress(&pqkvg, qkvg_buf);
    cudaGetSymbolAddress(&pxh, xhi_buf);
    cudaGetSymbolAddress(&pxl, xlo_buf);
    cudaGetSymbolAddress(&poh, ohi_buf);
    cudaGetSymbolAddress(&pol, olo_buf);
    cudaGetSymbolAddress(&pwch, wcat_hi);
    cudaGetSymbolAddress(&pwcl, wcat_lo);
    cudaGetSymbolAddress(&pwoh, wo_hi);
    cudaGetSymbolAddress(&pwol, wo_lo);

    cudaFuncSetAttribute(hmma_gemm,     cudaFuncAttributeMaxDynamicSharedMemorySize, 2 * BUFB);
    cudaFuncSetAttribute(out_kernel,    cudaFuncAttributeMaxDynamicSharedMemorySize, 85248);
    cudaFuncSetAttribute(chunkU_kernel, cudaFuncAttributeMaxDynamicSharedMemorySize, 51200);

    typedef __nv_bfloat16* bfp;
    typedef const __nv_bfloat16* cbf;
    bfp wch = (bfp)pwch, wcl = (bfp)pwcl;

    // prep (ordered so the fused GEMM is launch #6 -> ncu -s 5 -c 1 captures it)
    splitx_kernel<<<T_TOK * D_MODEL / 4 / 256, 256>>>(x, (bfp)pxh, (bfp)pxl,
                                                      T_TOK * D_MODEL / 4);          // 1
    tsplit_kernel<<<dim3(8, 16),  dim3(32, 8)>>>(Wq, wch,              wcl,              DKc, 0.125f); // 2
    tsplit_kernel<<<dim3(8, 16),  dim3(32, 8)>>>(Wk, wch + 256 * 512,  wcl + 256 * 512,  DKc, 1.0f);   // 3
    tsplit_kernel<<<dim3(16, 16), dim3(32, 8)>>>(Wv, wch + 512 * 512,  wcl + 512 * 512,  DVc, 1.0f);   // 4
    tsplit_kernel<<<dim3(16, 16), dim3(32, 8)>>>(Wg, wch + 1024 * 512, wcl + 1024 * 512, DVc, 1.0f);   // 5

    // fused q|k|v|g projection: C[T,1536]                                            // 6 (profiled)
    hmma_gemm<<<dim3(NQKVG / 128, T_TOK / 128), 256, 2 * BUFB>>>(
        (cbf)pxh, (cbf)pxl, (cbf)pwch, (cbf)pwcl, (float*)pqkvg, NQKVG, 1.0f);

    tsplit_kernel<<<dim3(16, 16), dim3(32, 8)>>>(Wo, (bfp)pwoh, (bfp)pwol, D_MODEL, 1.0f);
    t1_kernel<<<T_TOK / 64, 256>>>(x, Wgk1);
    decay_kernel<<<NCHUNK, 256>>>(Wgk2, bgk2);

    chunkU_kernel<<<dim3(NH, NCHUNK), 256, 51200>>>();
    scan_kernel<<<dim3(NH, 2, 16), 256>>>();
    out_kernel<<<dim3(NH, NCHUNK), 256, 85248>>>();

    hmma_gemm<<<dim3(D_MODEL / 128, T_TOK / 128), 256, 2 * BUFB>>>(
        (cbf)poh, (cbf)pol, (cbf)pwoh, (cbf)pwol, out, D_MODEL, 1.0f);
}

// round 17
// speedup vs baseline: 2.9771x; 1.2737x over previous
#include <cuda_runtime.h>
#include <cuda_fp16.h>
#include <cstdint>
#include <math.h>

#define T_TOK   32768      // B*S
#define D_MODEL 512
#define DKc     256
#define DVc     512
#define NH      4
#define HK      64
#define HV      128
#define CH      64
#define NCHUNK  512
#define GLR     16
#define NQKVG   1536       // 256 q + 256 k + 512 v + 512 g

// ---------------- scratch (device globals) ----------------------------------------
__device__ __align__(16) float qkvg_buf[(size_t)T_TOK*NQKVG];
__device__ __align__(16) float t1_buf [T_TOK*GLR];
__device__ __align__(16) float eg_buf [T_TOK*DKc];
__device__ __align__(16) float einv_buf[T_TOK*DKc];
__device__ __align__(16) float U_buf [(size_t)NCHUNK*NH*HK*HV];
__device__ __align__(16) float Hi_buf[(size_t)NCHUNK*NH*HK*HV];

__device__ __align__(16) __half xhi_buf[T_TOK*D_MODEL];
__device__ __align__(16) __half xlo_buf[T_TOK*D_MODEL];
__device__ __align__(16) __half ohi_buf[T_TOK*DVc];
__device__ __align__(16) __half olo_buf[T_TOK*DVc];
__device__ __align__(16) __half wcat_h [NQKVG*D_MODEL];   // fp16 weights (q|k|v|g)
__device__ __align__(16) __half wo_h   [D_MODEL*DVc];

// ================== FMA-only transcendentals (avoid the slow MUFU pipe) ===========
__device__ __forceinline__ float fexp(float x) {
    float n = rintf(x * 1.4426950408889634f);
    float r = fmaf(n, -0.693359375f, x);
    r = fmaf(n, 2.12194440054690583e-4f, r);
    float p = 1.3888888888e-3f;
    p = fmaf(p, r, 8.3333333333e-3f);
    p = fmaf(p, r, 4.1666666666e-2f);
    p = fmaf(p, r, 1.6666666666e-1f);
    p = fmaf(p, r, 0.5f);
    p = fmaf(p, r, 1.0f);
    p = fmaf(p, r, 1.0f);
    int ni = (int)n;
    return p * __int_as_float((ni + 127) << 23);
}
// log(1+u) for u in (0, 1]
__device__ __forceinline__ float flog1p(float u) {
    bool big = u > 0.4142135f;
    float w = big ? fmaf(0.5f, u, -0.5f) : u;
    float z = w * w;
    float p = 7.0376836292e-2f;
    p = fmaf(p, w, -1.1514610310e-1f);
    p = fmaf(p, w,  1.1676998740e-1f);
    p = fmaf(p, w, -1.2420140846e-1f);
    p = fmaf(p, w,  1.4249322787e-1f);
    p = fmaf(p, w, -1.6668057665e-1f);
    p = fmaf(p, w,  2.0000714765e-1f);
    p = fmaf(p, w, -2.4999993993e-1f);
    p = fmaf(p, w,  3.3333331174e-1f);
    float y = fmaf(w * z, p, -0.5f * z);
    float res = w + y;
    return big ? res + 0.69314718056f : res;
}
__device__ __forceinline__ float frcp(float x) {
    float r = __int_as_float(0x7EF311C3 - __float_as_int(x));
    r = r * fmaf(-x, r, 2.0f);
    r = r * fmaf(-x, r, 2.0f);
    r = r * fmaf(-x, r, 2.0f);
    return r;
}

// ================== HMMA machinery ================================================
__device__ __forceinline__ uint32_t s2u(const void* p) {
    uint32_t a;
    asm("{ .reg .u64 t; cvta.to.shared.u64 t, %1; cvt.u32.u64 %0, t; }" : "=r"(a) : "l"(p));
    return a;
}
#define LDSM4(r0, r1, r2, r3, addr) \
    asm volatile("ldmatrix.sync.aligned.m8n8.x4.shared.b16 {%0,%1,%2,%3}, [%4];" \
        : "=r"(r0), "=r"(r1), "=r"(r2), "=r"(r3) : "r"(addr))
#define MMA16816H(c, a, b0, b1) \
    asm volatile("mma.sync.aligned.m16n8k16.row.col.f32.f16.f16.f32 " \
        "{%0,%1,%2,%3}, {%4,%5,%6,%7}, {%8,%9}, {%0,%1,%2,%3};" \
        : "+f"((c)[0]), "+f"((c)[1]), "+f"((c)[2]), "+f"((c)[3]) \
        : "r"((a)[0]), "r"((a)[1]), "r"((a)[2]), "r"((a)[3]), "r"(b0), "r"(b1))
#define CP_ASYNC16(dst, src) \
    asm volatile("cp.async.cg.shared.global [%0], [%1], 16;" :: "r"(dst), "l"(src))
#define CP_COMMIT()  asm volatile("cp.async.commit_group;" ::: "memory")
#define CP_WAIT1()   asm volatile("cp.async.wait_group 1;" ::: "memory")
#define CP_WAIT0()   asm volatile("cp.async.wait_group 0;" ::: "memory")

#define ROWB   144
#define TILEB  18432            // 128*144
#define BUFB   36864            // A + B

// ================== fp16 2-pass HMMA GEMM =========================================
// C[M,N] = alpha * (Ahi+Alo)[M,512] @ Bh^T  (Bh fp16, K-major [N,512]).
// pass1 Ahi*Bh, pass2 Alo*Bh = exactly A*Bh; error = A*(B-Bh) ~ 2^-11 rel.
__global__ void __launch_bounds__(256, 2) hmma_gemm(
    const __half* __restrict__ Ahi, const __half* __restrict__ Alo,
    const __half* __restrict__ B,
    float* __restrict__ C, int N, float alpha)
{
    extern __shared__ char smem[];
    uint32_t sb = s2u(smem);
    int tid = threadIdx.x, lane = tid & 31, wid = tid >> 5;
    int m0 = blockIdx.y << 7, n0 = blockIdx.x << 7;
    int wm = wid & 1, wn = wid >> 1;

    float acc[4][4][4];
#pragma unroll
    for (int i = 0; i < 4; i++)
#pragma unroll
        for (int j = 0; j < 4; j++)
#pragma unroll
            for (int r = 0; r < 4; r++) acc[i][j][r] = 0.0f;

    int lrow  = tid >> 1;
    int lcb   = (tid & 1) * 4;
    uint32_t sa_st = lrow * ROWB + lcb * 16;

    auto stage = [&](int s, int buf) {
        int seg = s >> 3;                      // 0: Ahi pass, 1: Alo pass
        int kk  = (s & 7) << 6;
        const __half* Ap = seg ? Alo : Ahi;
        const __half* ga = Ap + (size_t)(m0 + lrow) * 512 + kk + lcb * 8;
        const __half* gb = B  + (size_t)(n0 + lrow) * 512 + kk + lcb * 8;
        uint32_t da = sb + buf * BUFB + sa_st;
        uint32_t db = da + TILEB;
#pragma unroll
        for (int i = 0; i < 4; i++) {
            CP_ASYNC16(da + i * 16, ga + i * 8);
            CP_ASYNC16(db + i * 16, gb + i * 8);
        }
    };

    int r8 = lane & 7, j = lane >> 3;
    uint32_t a_row = (uint32_t)(wm * 64 + (j & 1) * 8 + r8);
    uint32_t a_cb  = (uint32_t)((j >> 1) * 16);
    uint32_t b_row = (uint32_t)(wn * 32 + (j >> 1) * 8 + r8);
    uint32_t b_cb  = (uint32_t)((j & 1) * 16);

    stage(0, 0);
    CP_COMMIT();

    for (int s = 0; s < 16; s++) {
        int buf = s & 1;
        if (s < 15) { stage(s + 1, buf ^ 1); CP_COMMIT(); CP_WAIT1(); }
        else        { CP_WAIT0(); }
        __syncthreads();

        uint32_t abase = sb + buf * BUFB;
        uint32_t bbase = abase + TILEB;
#pragma unroll
        for (int kq = 0; kq < 4; kq++) {
            uint32_t kb = kq * 32;
            uint32_t ra[4][4], rb[2][4];
#pragma unroll
            for (int mt = 0; mt < 4; mt++) {
                uint32_t ad = abase + (a_row + mt * 16) * ROWB + kb + a_cb;
                LDSM4(ra[mt][0], ra[mt][1], ra[mt][2], ra[mt][3], ad);
            }
#pragma unroll
            for (int bt = 0; bt < 2; bt++) {
                uint32_t bd = bbase + (b_row + bt * 16) * ROWB + kb + b_cb;
                LDSM4(rb[bt][0], rb[bt][1], rb[bt][2], rb[bt][3], bd);
            }
#pragma unroll
            for (int mt = 0; mt < 4; mt++)
#pragma unroll
                for (int nt = 0; nt < 4; nt++)
                    MMA16816H(acc[mt][nt], ra[mt],
                              rb[nt >> 1][(nt & 1) * 2], rb[nt >> 1][(nt & 1) * 2 + 1]);
        }
        __syncthreads();
    }

    int erow = lane >> 2;
    int ecol = (lane & 3) * 2;
#pragma unroll
    for (int mt = 0; mt < 4; mt++) {
        int row = m0 + wm * 64 + mt * 16 + erow;
#pragma unroll
        for (int nt = 0; nt < 4; nt++) {
            int col = n0 + wn * 32 + nt * 8 + ecol;
            *(float2*)&C[(size_t)row * N + col] =
                make_float2(alpha * acc[mt][nt][0], alpha * acc[mt][nt][1]);
            *(float2*)&C[(size_t)(row + 8) * N + col] =
                make_float2(alpha * acc[mt][nt][2], alpha * acc[mt][nt][3]);
        }
    }
}

// ---------------- prep: split fp32 -> fp16 hi/lo ----------------------------------
__global__ void __launch_bounds__(256) splitx_kernel(
    const float* __restrict__ src, __half* __restrict__ hi,
    __half* __restrict__ lo, int n4)
{
    int i = blockIdx.x * 256 + threadIdx.x;
    if (i >= n4) return;
    float4 v = ((const float4*)src)[i];
    float a[4] = {v.x, v.y, v.z, v.w};
    __half h[4], l[4];
#pragma unroll
    for (int j = 0; j < 4; j++) {
        h[j] = __float2half(a[j]);
        l[j] = __float2half(a[j] - __half2float(h[j]));
    }
    __half2 h01 = __halves2half2(h[0], h[1]), h23 = __halves2half2(h[2], h[3]);
    __half2 l01 = __halves2half2(l[0], l[1]), l23 = __halves2half2(l[2], l[3]);
    uint2 ph, pl;
    ph.x = *(uint32_t*)&h01; ph.y = *(uint32_t*)&h23;
    pl.x = *(uint32_t*)&l01; pl.y = *(uint32_t*)&l23;
    *(uint2*)&hi[(size_t)i * 4] = ph;
    *(uint2*)&lo[(size_t)i * 4] = pl;
}

// ---------------- prep: ALL weights transpose + fp16 in one launch ----------------
// tile id t: Wq[0..8) Wk[8..16) Wv[16..32) Wg[32..48) Wo[48..64), each 32 n-cols.
__global__ void tsplit_all(const float* __restrict__ Wq, const float* __restrict__ Wk,
                           const float* __restrict__ Wv, const float* __restrict__ Wg,
                           const float* __restrict__ Wo,
                           __half* __restrict__ wcat, __half* __restrict__ wo)
{
    __shared__ float t[32][33];
    int tb = blockIdx.x;
    const float* W; __half* T; int N; float scale; int n0;
    if (tb < 8)       { W = Wq; T = wcat;              N = 256; scale = 0.125f; n0 = tb * 32; }
    else if (tb < 16) { W = Wk; T = wcat + 256 * 512;  N = 256; scale = 1.0f;   n0 = (tb - 8) * 32; }
    else if (tb < 32) { W = Wv; T = wcat + 512 * 512;  N = 512; scale = 1.0f;   n0 = (tb - 16) * 32; }
    else if (tb < 48) { W = Wg; T = wcat + 1024 * 512; N = 512; scale = 1.0f;   n0 = (tb - 32) * 32; }
    else              { W = Wo; T = wo;                N = 512; scale = 1.0f;   n0 = (tb - 48) * 32; }

    int k0 = blockIdx.y * 32;
    int lx = threadIdx.x, ly = threadIdx.y;   // 32 x 8
#pragma unroll
    for (int i = 0; i < 4; i++) {
        int k = ly + i * 8;
        t[k][lx] = W[(size_t)(k0 + k) * N + n0 + lx];
    }
    __syncthreads();
#pragma unroll
    for (int i = 0; i < 4; i++) {
        int n = ly + i * 8;
        T[(size_t)(n0 + n) * 512 + k0 + lx] = __float2half(t[lx][n] * scale);
    }
}

// ---------------- t1 = x @ Wgk1 : [T,16], W in smem -------------------------------
__global__ void __launch_bounds__(256) t1_kernel(
    const float* __restrict__ x, const float* __restrict__ W)
{
    __shared__ float Ws[512 * 16];
    int tid = threadIdx.x;
    for (int i = tid; i < 512 * 16; i += 256) Ws[i] = W[i];
    __syncthreads();

    int row = blockIdx.x * 64 + (tid >> 2);
    int j0 = (tid & 3) << 2;
    const float4* xr = (const float4*)(x + (size_t)row * 512);
    float a0 = 0, a1 = 0, a2 = 0, a3 = 0;
#pragma unroll 4
    for (int k4 = 0; k4 < 128; k4++) {
        float4 xv = xr[k4];
        int kb = k4 << 2;
        float4 w0 = *(const float4*)&Ws[(kb + 0) * 16 + j0];
        float4 w1 = *(const float4*)&Ws[(kb + 1) * 16 + j0];
        float4 w2 = *(const float4*)&Ws[(kb + 2) * 16 + j0];
        float4 w3 = *(const float4*)&Ws[(kb + 3) * 16 + j0];
        a0 = fmaf(xv.x, w0.x, fmaf(xv.y, w1.x, fmaf(xv.z, w2.x, fmaf(xv.w, w3.x, a0))));
        a1 = fmaf(xv.x, w0.y, fmaf(xv.y, w1.y, fmaf(xv.z, w2.y, fmaf(xv.w, w3.y, a1))));
        a2 = fmaf(xv.x, w0.z, fmaf(xv.y, w1.z, fmaf(xv.z, w2.z, fmaf(xv.w, w3.z, a2))));
        a3 = fmaf(xv.x, w0.w, fmaf(xv.y, w1.w, fmaf(xv.z, w2.w, fmaf(xv.w, w3.w, a3))));
    }
    *(float4*)&t1_buf[(size_t)row * GLR + j0] = make_float4(a0, a1, a2, a3);
}

// ---------------- decay: gk + in-chunk cumsum + exp, all FMA-pipe -----------------
__global__ void __launch_bounds__(256) decay_kernel(
    const float* __restrict__ Wgk2, const float* __restrict__ bgk2)
{
    __shared__ float t1s[64][17];
    int gc = blockIdx.x, d = threadIdx.x;
    int t0 = gc << 6;
#pragma unroll
    for (int i = 0; i < 4; i++) {
        int lin = d + (i << 8);
        int r = lin >> 4, c = lin & 15;
        t1s[r][c] = t1_buf[(size_t)(t0 + r) * GLR + c];
    }
    float w[16];
#pragma unroll
    for (int r = 0; r < 16; r++) w[r] = Wgk2[r * DKc + d];
    float b = bgk2[d];
    __syncthreads();

    float G = 0.0f;
    for (int t = 0; t < 64; t++) {
        float s = b;
#pragma unroll
        for (int r = 0; r < 16; r++) s = fmaf(t1s[t][r], w[r], s);
        float u = fexp(-fabsf(s));
        float ls = fminf(s, 0.0f) - flog1p(u);
        G = fmaf(ls, 0.0625f, G);
        size_t idx = (size_t)(t0 + t) * DKc + d;
        eg_buf[idx]   = fexp(G);
        einv_buf[idx] = fexp(-G);
    }
}

// ---------------- per-chunk U = sum_t e^(Glast-Gt) k_t (x) v_t --------------------
__global__ void __launch_bounds__(256, 2) chunkU_kernel()
{
    extern __shared__ float sm[];
    float* kt = sm;            // [64][68]
    float* vt = sm + 4352;     // [64][132]
    int h = blockIdx.x, gc = blockIdx.y;
    int tid = threadIdx.x;
    int tx = tid & 15, ty = tid >> 4;
    int t0 = gc << 6;

#pragma unroll
    for (int i = 0; i < 16; i++) {
        int lin = tid + (i << 8);
        int r = lin >> 6, c = lin & 63;
        float kv   = qkvg_buf[(size_t)(t0 + r) * NQKVG + 256 + h * HK + c];
        float ei   = einv_buf[(size_t)(t0 + r) * DKc + h * HK + c];
        float egl  = eg_buf[(size_t)(t0 + 63) * DKc + h * HK + c];
        kt[r * 68 + c] = kv * (egl * ei);
    }
#pragma unroll
    for (int i = 0; i < 8; i++) {
        int q = tid + (i << 8);
        int r = q >> 5, c4 = (q & 31) << 2;
        *(float4*)&vt[r * 132 + c4] =
            *(const float4*)&qkvg_buf[(size_t)(t0 + r) * NQKVG + 512 + h * HV + c4];
    }
    __syncthreads();

    float acc[4][8];
#pragma unroll
    for (int i = 0; i < 4; i++)
#pragma unroll
        for (int j = 0; j < 8; j++) acc[i][j] = 0.0f;

#pragma unroll 4
    for (int t = 0; t < 64; t++) {
        float4 a0 = *(const float4*)&kt[t * 68 + (ty << 2)];
        float4 b0 = *(const float4*)&vt[t * 132 + (tx << 2)];
        float4 b1 = *(const float4*)&vt[t * 132 + 64 + (tx << 2)];
        float av[4] = {a0.x, a0.y, a0.z, a0.w};
        float bv[8] = {b0.x, b0.y, b0.z, b0.w, b1.x, b1.y, b1.z, b1.w};
#pragma unroll
        for (int i = 0; i < 4; i++)
#pragma unroll
            for (int j = 0; j < 8; j++) acc[i][j] += av[i] * bv[j];
    }

    size_t ub = ((size_t)gc * NH + h) << 13;
#pragma unroll
    for (int i = 0; i < 4; i++) {
        int row = (ty << 2) + i;
        *(float4*)&U_buf[ub + row * 128 + (tx << 2)] =
            make_float4(acc[i][0], acc[i][1], acc[i][2], acc[i][3]);
        *(float4*)&U_buf[ub + row * 128 + 64 + (tx << 2)] =
            make_float4(acc[i][4], acc[i][5], acc[i][6], acc[i][7]);
    }
}

// ---------------- sequential chunk scan, sync-free, 16 v-slices -------------------
__global__ void __launch_bounds__(256) scan_kernel()
{
    int h = blockIdx.x, b = blockIdx.y, sl = blockIdx.z;   // sl in 0..15
    int tid = threadIdx.x;
    int k = tid >> 2;                       // 0..63 (key dim)
    int voff = (sl << 3) + ((tid & 3) << 1);   // 8-col slice, 2 floats/thread

    float2 st = make_float2(0.f, 0.f);

#pragma unroll 4
    for (int c = 0; c < 256; c++) {
        int gc = (b << 8) + c;
        float lam = eg_buf[(size_t)((gc << 6) + 63) * DKc + h * HK + k];
        size_t base = (((size_t)gc * NH + h) << 13) + k * 128 + voff;
        float2 u = *(const float2*)&U_buf[base];
        *(float2*)&Hi_buf[base] = st;
        st.x = fmaf(lam, st.x, u.x);
        st.y = fmaf(lam, st.y, u.y);
    }
}

// ---------------- per-chunk output + shuffle-LN + SiLU, writes fp16 hi/lo ---------
__global__ void __launch_bounds__(256, 2) out_kernel()
{
    extern __shared__ float sm[];
    float* qs = sm;                 // [64][68]
    float* ks = sm + 4352;          // [64][65]
    float* As = sm + 8512;          // [64][68]
    float* vs = sm + 12864;         // [64][132]

    int h = blockIdx.x, gc = blockIdx.y;
    int tid = threadIdx.x;
    int tx = tid & 15, ty = tid >> 4;
    int t0 = gc << 6;

#pragma unroll
    for (int i = 0; i < 16; i++) {
        int lin = tid + (i << 8);
        int r = lin >> 6, c = lin & 63;
        size_t gidx = (size_t)(t0 + r) * NQKVG + h * HK + c;
        size_t eidx = (size_t)(t0 + r) * DKc + h * HK + c;
        qs[r * 68 + c] = qkvg_buf[gidx]       * eg_buf[eidx];
        ks[r * 65 + c] = qkvg_buf[gidx + 256] * einv_buf[eidx];
    }
#pragma unroll
    for (int i = 0; i < 8; i++) {
        int q = tid + (i << 8);
        int r = q >> 5, c4 = (q & 31) << 2;
        *(float4*)&vs[r * 132 + c4] =
            *(const float4*)&qkvg_buf[(size_t)(t0 + r) * NQKVG + 512 + h * HV + c4];
    }
    __syncthreads();

    {
        int tt = (tid >> 4) << 2;
        int ss = (tid & 15) << 2;
        float a[4][4];
#pragma unroll
        for (int i = 0; i < 4; i++)
#pragma unroll
            for (int j = 0; j < 4; j++) a[i][j] = 0.0f;
#pragma unroll 4
        for (int k = 0; k < 64; k++) {
            float qv[4], kv[4];
#pragma unroll
            for (int i = 0; i < 4; i++) { qv[i] = qs[(tt + i) * 68 + k]; kv[i] = ks[(ss + i) * 65 + k]; }
#pragma unroll
            for (int i = 0; i < 4; i++)
#pragma unroll
                for (int j = 0; j < 4; j++) a[i][j] += qv[i] * kv[j];
        }
#pragma unroll
        for (int i = 0; i < 4; i++)
#pragma unroll
            for (int j = 0; j < 4; j++)
                As[(tt + i) * 68 + ss + j] = (ss + j <= tt + i) ? a[i][j] : 0.0f;
    }
    __syncthreads();

    float acc[4][8];
#pragma unroll
    for (int i = 0; i < 4; i++)
#pragma unroll
        for (int j = 0; j < 8; j++) acc[i][j] = 0.0f;

#pragma unroll 4
    for (int s = 0; s < 64; s++) {
        float4 b0 = *(const float4*)&vs[s * 132 + (tx << 2)];
        float4 b1 = *(const float4*)&vs[s * 132 + 64 + (tx << 2)];
        float av[4];
#pragma unroll
        for (int i = 0; i < 4; i++) av[i] = As[((ty << 2) + i) * 68 + s];
        float bv[8] = {b0.x, b0.y, b0.z, b0.w, b1.x, b1.y, b1.z, b1.w};
#pragma unroll
        for (int i = 0; i < 4; i++)
#pragma unroll
            for (int j = 0; j < 8; j++) acc[i][j] += av[i] * bv[j];
    }
    __syncthreads();

    {
        size_t hb = ((size_t)gc * NH + h) << 13;
#pragma unroll
        for (int i = 0; i < 8; i++) {
            int q = tid + (i << 8);
            int r = q >> 5, c4 = (q & 31) << 2;
            *(float4*)&vs[r * 132 + c4] = *(const float4*)&Hi_buf[hb + r * 128 + c4];
        }
    }
    __syncthreads();

#pragma unroll 4
    for (int k = 0; k < 64; k++) {
        float4 b0 = *(const float4*)&vs[k * 132 + (tx << 2)];
        float4 b1 = *(const float4*)&vs[k * 132 + 64 + (tx << 2)];
        float av[4];
#pragma unroll
        for (int i = 0; i < 4; i++) av[i] = qs[((ty << 2) + i) * 68 + k];
        float bv[8] = {b0.x, b0.y, b0.z, b0.w, b1.x, b1.y, b1.z, b1.w};
#pragma unroll
        for (int i = 0; i < 4; i++)
#pragma unroll
            for (int j = 0; j < 8; j++) acc[i][j] += av[i] * bv[j];
    }

    // shuffle-LN epilogue (xor 1,2,4,8 stays within the 16-lane tx group)
#pragma unroll
    for (int i = 0; i < 4; i++) {
        float s1 = 0.0f;
#pragma unroll
        for (int j = 0; j < 8; j++) s1 += acc[i][j];
        s1 += __shfl_xor_sync(0xffffffffu, s1, 1);
        s1 += __shfl_xor_sync(0xffffffffu, s1, 2);
        s1 += __shfl_xor_sync(0xffffffffu, s1, 4);
        s1 += __shfl_xor_sync(0xffffffffu, s1, 8);
        float mu = s1 * (1.0f / 128.0f);
        float s2 = 0.0f;
#pragma unroll
        for (int j = 0; j < 8; j++) { float d = acc[i][j] - mu; s2 += d * d; }
        s2 += __shfl_xor_sync(0xffffffffu, s2, 1);
        s2 += __shfl_xor_sync(0xffffffffu, s2, 2);
        s2 += __shfl_xor_sync(0xffffffffu, s2, 4);
        s2 += __shfl_xor_sync(0xffffffffu, s2, 8);
        float rstd = rsqrtf(s2 * (1.0f / 128.0f) + 1e-5f);

        int row = (ty << 2) + i;
        size_t rbase = (size_t)(t0 + row);
        size_t gb0 = rbase * NQKVG + 1024 + h * HV + (tx << 2);
        size_t ob0 = rbase * DVc + h * HV + (tx << 2);

#pragma unroll
        for (int half = 0; half < 2; half++) {
            float4 g4 = *(const float4*)&qkvg_buf[gb0 + half * 64];
            float gv[4] = {g4.x, g4.y, g4.z, g4.w};
            __half hh[4], ll[4];
#pragma unroll
            for (int j = 0; j < 4; j++) {
                float gg = gv[j];
                float sg = gg * frcp(1.0f + fexp(-gg));
                float val = (acc[i][half * 4 + j] - mu) * rstd * sg;
                hh[j] = __float2half(val);
                ll[j] = __float2half(val - __half2float(hh[j]));
            }
            __half2 h01 = __halves2half2(hh[0], hh[1]), h23 = __halves2half2(hh[2], hh[3]);
            __half2 l01 = __halves2half2(ll[0], ll[1]), l23 = __halves2half2(ll[2], ll[3]);
            uint2 ph, pl;
            ph.x = *(uint32_t*)&h01; ph.y = *(uint32_t*)&h23;
            pl.x = *(uint32_t*)&l01; pl.y = *(uint32_t*)&l23;
            *(uint2*)&ohi_buf[ob0 + half * 64] = ph;
            *(uint2*)&olo_buf[ob0 + half * 64] = pl;
        }
    }
}

// ---------------------------------------------------------------------------------
extern "C" void kernel_launch(void* const* d_in, const int* in_sizes, int n_in,
                              void* d_out, int out_size)
{
    const float* x    = (const float*)d_in[0];
    const float* Wq   = (const float*)d_in[1];
    const float* Wk   = (const float*)d_in[2];
    const float* Wv   = (const float*)d_in[3];
    const float* Wg   = (const float*)d_in[4];
    const float* Wgk1 = (const float*)d_in[5];
    const float* Wgk2 = (const float*)d_in[6];
    const float* bgk2 = (const float*)d_in[7];
    const float* Wo   = (const float*)d_in[8];
    float* out = (float*)d_out;
    (void)in_sizes; (void)n_in; (void)out_size;

    void *pqkvg, *pxh, *pxl, *poh, *pol, *pwc, *pwo;
    cudaGetSymbolAddress(&pqkvg, qkvg_buf);
    cudaGetSymbolAddress(&pxh, xhi_buf);
    cudaGetSymbolAddress(&pxl, xlo_buf);
    cudaGetSymbolAddress(&poh, ohi_buf);
    cudaGetSymbolAddress(&pol, olo_buf);
    cudaGetSymbolAddress(&pwc, wcat_h);
    cudaGetSymbolAddress(&pwo, wo_h);

    cudaFuncSetAttribute(hmma_gemm,     cudaFuncAttributeMaxDynamicSharedMemorySize, 2 * BUFB);
    cudaFuncSetAttribute(out_kernel,    cudaFuncAttributeMaxDynamicSharedMemorySize, 85248);
    cudaFuncSetAttribute(chunkU_kernel, cudaFuncAttributeMaxDynamicSharedMemorySize, 51200);

    typedef __half* hp;
    typedef const __half* chp;

    // launches ordered so hmma_gemm is my #4 (ncu's skip appears to include
    // ~2 harness-side launches; this aims the -s 5 -c 1 capture at the GEMM)
    splitx_kernel<<<T_TOK * D_MODEL / 4 / 256, 256>>>(x, (hp)pxh, (hp)pxl,
                                                      T_TOK * D_MODEL / 4);              // 1
    tsplit_all<<<dim3(64, 16), dim3(32, 8)>>>(Wq, Wk, Wv, Wg, Wo, (hp)pwc, (hp)pwo);     // 2
    t1_kernel<<<T_TOK / 64, 256>>>(x, Wgk1);                                             // 3

    // fused q|k|v|g projection: C[T,1536]                                               // 4
    hmma_gemm<<<dim3(NQKVG / 128, T_TOK / 128), 256, 2 * BUFB>>>(
        (chp)pxh, (chp)pxl, (chp)pwc, (float*)pqkvg, NQKVG, 1.0f);

    decay_kernel<<<NCHUNK, 256>>>(Wgk2, bgk2);                                           // 5
    chunkU_kernel<<<dim3(NH, NCHUNK), 256, 51200>>>();                                   // 6
    scan_kernel<<<dim3(NH, 2, 16), 256>>>();                                             // 7
    out_kernel<<<dim3(NH, NCHUNK), 256, 85248>>>();                                      // 8

    hmma_gemm<<<dim3(D_MODEL / 128, T_TOK / 128), 256, 2 * BUFB>>>(
        (chp)poh, (chp)pol, (chp)pwo, out, D_MODEL, 1.0f);                               // 9
}